// round 5
// baseline (speedup 1.0000x reference)
#include <cuda_runtime.h>
#include <math.h>
#include <stdint.h>

#define NCOMP 20000
#define NMEAS 64
#define SDIM 6
#define MDIM 3
#define NPART 128
#define LOG2PI 1.8378770664093453f
#define PD_C 0.98f
#define CLUTTER_C 1e-4f

// Output layout (concatenated, float32):
//   posterior_ensemble  [64,20000,6]   offset 0
//   normalized_weights  [64,20000]     offset 7,680,000
//   posterior_covs      [64,20000,6,6] offset 8,960,000
#define ENS_OFF 0
#define W_OFF   (NMEAS * NCOMP * SDIM)
#define COV_OFF (W_OFF + NMEAS * NCOMP)

// posterior_covs geometry in bytes
#define COV_TABLE_B  (NCOMP * 36 * 4)        // 2,880,000 B (one copy)
#define CTILE_B      18000                    // tile bytes (divides table: 160 tiles)
#define CTILES       (COV_TABLE_B / CTILE_B)  // 160

// ---------------- device scratch ----------------
__device__ double g_part[NPART * 27];
__device__ float  g_P[36];
__device__ float  g_ybar[NCOMP * 3];
__device__ float  g_K[NCOMP * 18];
__device__ float  g_Sinv[NCOMP * 6];
__device__ float  g_c0[NCOMP];
__device__ float4 g_postcov4[NCOMP * 9];
__device__ float  g_terms[NMEAS * NCOMP];
__device__ float  g_logden[NMEAS];

// ---------------- kernel 1a: partial sums for empirical covariance --------
__global__ void k_cov_partial(const float* __restrict__ means) {
    double v[27];
#pragma unroll
    for (int k = 0; k < 27; k++) v[k] = 0.0;

    for (int r = blockIdx.x * blockDim.x + threadIdx.x; r < NCOMP;
         r += gridDim.x * blockDim.x) {
        float x[6];
#pragma unroll
        for (int i = 0; i < 6; i++) x[i] = means[r * 6 + i];
#pragma unroll
        for (int i = 0; i < 6; i++) v[i] += (double)x[i];
        int idx = 6;
#pragma unroll
        for (int i = 0; i < 6; i++)
#pragma unroll
            for (int j = i; j < 6; j++)
                v[idx++] += (double)x[i] * (double)x[j];
    }

    int lane = threadIdx.x & 31;
    int warp = threadIdx.x >> 5;
    __shared__ double sh[8][27];
#pragma unroll
    for (int k = 0; k < 27; k++) {
        double s = v[k];
#pragma unroll
        for (int off = 16; off > 0; off >>= 1)
            s += __shfl_down_sync(0xffffffffu, s, off);
        if (lane == 0) sh[warp][k] = s;
    }
    __syncthreads();
    if (threadIdx.x < 27) {
        double s = 0.0;
#pragma unroll
        for (int w = 0; w < 8; w++) s += sh[w][threadIdx.x];
        g_part[blockIdx.x * 27 + threadIdx.x] = s;
    }
}

// ---------------- kernel 1b: finalize P ----------------
__global__ void k_cov_final() {
    __shared__ double acc[27];
    int k = threadIdx.x;
    if (k < 27) {
        double a = 0.0;
        for (int b = 0; b < NPART; b++) a += g_part[b * 27 + k];
        acc[k] = a;
    }
    __syncthreads();
    if (threadIdx.x == 0) {
        double mean[6];
        for (int i = 0; i < 6; i++) mean[i] = acc[i] / (double)NCOMP;
        double cov[6][6];
        int idx = 6;
        for (int i = 0; i < 6; i++)
            for (int j = i; j < 6; j++) {
                double c = (acc[idx] - (double)NCOMP * mean[i] * mean[j]) /
                           (double)(NCOMP - 1);
                cov[i][j] = c;
                cov[j][i] = c;
                idx++;
            }
        double bw = pow(4.0 / ((double)NCOMP * (SDIM + 2)), 2.0 / (SDIM + 4));
        for (int i = 0; i < 6; i++)
            for (int j = 0; j < 6; j++) {
                double d = (double)(i - j);
                double loc = exp(-(d * d) / (2.0 * 3.0 * 3.0));
                g_P[i * 6 + j] = (float)(bw * cov[i][j] * loc);
            }
    }
}

// ---------------- kernel 2: per-component linearization ----------------
__global__ void k_pern(const float* __restrict__ means,
                       const float* __restrict__ wts,
                       const float* __restrict__ Rm) {
    __shared__ float Ps[36];
    __shared__ float Rs[9];
    int tid = threadIdx.x;
    if (tid < 36) Ps[tid] = g_P[tid];
    if (tid < 9)  Rs[tid] = Rm[tid];
    __syncthreads();

    int n = blockIdx.x * blockDim.x + tid;
    if (n >= NCOMP) return;

    float mu[6];
#pragma unroll
    for (int i = 0; i < 6; i++) mu[i] = means[n * 6 + i];
    float x = mu[0], y = mu[1], z = mu[2];

    float rxy2 = x * x + y * y;
    float rho2 = rxy2 + z * z;
    float rho  = sqrtf(rho2);
    float rxy  = sqrtf(rxy2);

    float yb0 = rho;
    float yb1 = atan2f(y, x);
    float yb2 = asinf(z / rho);

    float H[3][3];
    float irho = 1.0f / rho;
    H[0][0] = x * irho; H[0][1] = y * irho; H[0][2] = z * irho;
    float irxy2 = 1.0f / rxy2;
    H[1][0] = -y * irxy2; H[1][1] = x * irxy2; H[1][2] = 0.0f;
    float den = 1.0f / (rho2 * rxy);
    H[2][0] = -x * z * den; H[2][1] = -y * z * den; H[2][2] = rxy / rho2;

    float PHt[6][3];
#pragma unroll
    for (int i = 0; i < 6; i++)
#pragma unroll
        for (int k = 0; k < 3; k++)
            PHt[i][k] = Ps[i * 6 + 0] * H[k][0] + Ps[i * 6 + 1] * H[k][1] +
                        Ps[i * 6 + 2] * H[k][2];

    float Sf[3][3];
#pragma unroll
    for (int k = 0; k < 3; k++)
#pragma unroll
        for (int l = 0; l < 3; l++)
            Sf[k][l] = H[k][0] * PHt[0][l] + H[k][1] * PHt[1][l] +
                       H[k][2] * PHt[2][l] + Rs[k * 3 + l];

    double d00 = Sf[0][0], d01 = 0.5 * ((double)Sf[0][1] + Sf[1][0]);
    double d02 = 0.5 * ((double)Sf[0][2] + Sf[2][0]);
    double d11 = Sf[1][1], d12 = 0.5 * ((double)Sf[1][2] + Sf[2][1]);
    double d22 = Sf[2][2];
    double c00 = d11 * d22 - d12 * d12;
    double c01 = d02 * d12 - d01 * d22;
    double c02 = d01 * d12 - d02 * d11;
    double det = d00 * c00 + d01 * c01 + d02 * c02;
    double idet = 1.0 / det;
    float i00 = (float)(c00 * idet);
    float i01 = (float)(c01 * idet);
    float i02 = (float)(c02 * idet);
    float i11 = (float)((d00 * d22 - d02 * d02) * idet);
    float i12 = (float)((d01 * d02 - d00 * d12) * idet);
    float i22 = (float)((d00 * d11 - d01 * d01) * idet);
    float logdet = logf((float)det);

    float K[6][3];
#pragma unroll
    for (int i = 0; i < 6; i++) {
        K[i][0] = PHt[i][0] * i00 + PHt[i][1] * i01 + PHt[i][2] * i02;
        K[i][1] = PHt[i][0] * i01 + PHt[i][1] * i11 + PHt[i][2] * i12;
        K[i][2] = PHt[i][0] * i02 + PHt[i][1] * i12 + PHt[i][2] * i22;
    }

    float KH[6][3];
#pragma unroll
    for (int i = 0; i < 6; i++)
#pragma unroll
        for (int j = 0; j < 3; j++)
            KH[i][j] = K[i][0] * H[0][j] + K[i][1] * H[1][j] + K[i][2] * H[2][j];

    float* pc = reinterpret_cast<float*>(g_postcov4);
#pragma unroll
    for (int i = 0; i < 6; i++)
#pragma unroll
        for (int j = 0; j < 6; j++) {
            float v = Ps[i * 6 + j] -
                      (KH[i][0] * Ps[0 * 6 + j] + KH[i][1] * Ps[1 * 6 + j] +
                       KH[i][2] * Ps[2 * 6 + j]);
            pc[n * 36 + i * 6 + j] = v;
        }

    g_ybar[n * 3 + 0] = yb0;
    g_ybar[n * 3 + 1] = yb1;
    g_ybar[n * 3 + 2] = yb2;
#pragma unroll
    for (int i = 0; i < 6; i++) {
        g_K[n * 18 + i * 3 + 0] = K[i][0];
        g_K[n * 18 + i * 3 + 1] = K[i][1];
        g_K[n * 18 + i * 3 + 2] = K[i][2];
    }
    g_Sinv[n * 6 + 0] = i00; g_Sinv[n * 6 + 1] = i01; g_Sinv[n * 6 + 2] = i02;
    g_Sinv[n * 6 + 3] = i11; g_Sinv[n * 6 + 4] = i12; g_Sinv[n * 6 + 5] = i22;
    g_c0[n] = logf(PD_C) + logf(wts[n]) - 0.5f * (logdet + 3.0f * LOG2PI);
}

// ---------------- kernel 3: per (m,n) update; m split across blockIdx.y ---
#define MSPLIT 8
#define MCHUNK (NMEAS / MSPLIT)    // 8
__global__ void k_update(const float* __restrict__ means,
                         const float* __restrict__ meas,
                         const int* __restrict__ mask,
                         float* __restrict__ out) {
    __shared__ float zm[MCHUNK * 3];
    __shared__ int mk[MCHUNK];
    int tid = threadIdx.x;
    int m0 = blockIdx.y * MCHUNK;
    if (tid < MCHUNK * 3) zm[tid] = meas[m0 * 3 + tid];
    if (tid < MCHUNK)     mk[tid] = mask[m0 + tid];
    __syncthreads();

    int n = blockIdx.x * blockDim.x + tid;
    if (n >= NCOMP) return;

    float mu[6];
#pragma unroll
    for (int i = 0; i < 6; i++) mu[i] = means[n * 6 + i];
    float yb0 = g_ybar[n * 3 + 0];
    float yb1 = g_ybar[n * 3 + 1];
    float yb2 = g_ybar[n * 3 + 2];
    float K[18];
#pragma unroll
    for (int i = 0; i < 18; i++) K[i] = g_K[n * 18 + i];
    float s00 = g_Sinv[n * 6 + 0], s01 = g_Sinv[n * 6 + 1],
          s02 = g_Sinv[n * 6 + 2], s11 = g_Sinv[n * 6 + 3],
          s12 = g_Sinv[n * 6 + 4], s22 = g_Sinv[n * 6 + 5];
    float c0 = g_c0[n];

#pragma unroll
    for (int mm = 0; mm < MCHUNK; mm++) {
        int m = m0 + mm;
        float r0 = yb0 - zm[mm * 3 + 0];
        float r1 = yb1 - zm[mm * 3 + 1];
        float r2 = yb2 - zm[mm * 3 + 2];
        float maha = s00 * r0 * r0 + s11 * r1 * r1 + s22 * r2 * r2 +
                     2.0f * (s01 * r0 * r1 + s02 * r0 * r2 + s12 * r1 * r2);
        g_terms[m * NCOMP + n] = c0 - 0.5f * maha;

        bool on = (mk[mm] != 0);
        float p0 = 0.f, p1 = 0.f, p2 = 0.f, p3 = 0.f, p4 = 0.f, p5 = 0.f;
        if (on) {
            p0 = mu[0] - (K[0]  * r0 + K[1]  * r1 + K[2]  * r2);
            p1 = mu[1] - (K[3]  * r0 + K[4]  * r1 + K[5]  * r2);
            p2 = mu[2] - (K[6]  * r0 + K[7]  * r1 + K[8]  * r2);
            p3 = mu[3] - (K[9]  * r0 + K[10] * r1 + K[11] * r2);
            p4 = mu[4] - (K[12] * r0 + K[13] * r1 + K[14] * r2);
            p5 = mu[5] - (K[15] * r0 + K[16] * r1 + K[17] * r2);
        }
        float2* dst = reinterpret_cast<float2*>(out + ENS_OFF +
                                                (size_t)(m * NCOMP + n) * 6);
        __stcs(&dst[0], make_float2(p0, p1));
        __stcs(&dst[1], make_float2(p2, p3));
        __stcs(&dst[2], make_float2(p4, p5));
    }
}

// ---------------- kernel 4: per-measurement logsumexp ----------------
__global__ void k_lse() {
    int m = blockIdx.x;
    int tid = threadIdx.x;
    int lane = tid & 31, warp = tid >> 5;
    __shared__ float sh[32];

    float mx = -3.4e38f;
    for (int n = tid; n < NCOMP; n += 1024)
        mx = fmaxf(mx, g_terms[m * NCOMP + n]);
#pragma unroll
    for (int off = 16; off > 0; off >>= 1)
        mx = fmaxf(mx, __shfl_down_sync(0xffffffffu, mx, off));
    if (lane == 0) sh[warp] = mx;
    __syncthreads();
    if (warp == 0) {
        float v = sh[lane];
#pragma unroll
        for (int off = 16; off > 0; off >>= 1)
            v = fmaxf(v, __shfl_down_sync(0xffffffffu, v, off));
        if (lane == 0) sh[0] = v;
    }
    __syncthreads();
    float bm = sh[0];
    __syncthreads();

    float sum = 0.0f;
    for (int n = tid; n < NCOMP; n += 1024)
        sum += expf(g_terms[m * NCOMP + n] - bm);
#pragma unroll
    for (int off = 16; off > 0; off >>= 1)
        sum += __shfl_down_sync(0xffffffffu, sum, off);
    if (lane == 0) sh[warp] = sum;
    __syncthreads();
    if (warp == 0) {
        float v = sh[lane];
#pragma unroll
        for (int off = 16; off > 0; off >>= 1)
            v += __shfl_down_sync(0xffffffffu, v, off);
        if (lane == 0) {
            float lse = bm + logf(v);
            float a = logf(CLUTTER_C);
            float hi = fmaxf(a, lse), lo = fminf(a, lse);
            g_logden[m] = hi + log1pf(expf(lo - hi));
        }
    }
}

// ---------------- kernel 5: normalized weights ----------------
__global__ void k_weights(const int* __restrict__ mask,
                          float* __restrict__ out) {
    int i = blockIdx.x * blockDim.x + threadIdx.x;
    if (i >= NMEAS * NCOMP) return;
    int m = i / NCOMP;
    float w = (mask[m] != 0) ? expf(g_terms[i] - g_logden[m]) : 0.0f;
    __stcs(out + W_OFF + i, w);
}

// ---------------- kernel 6: covariance broadcast via TMA bulk stores ------
// Each block: load one CTILE_B-byte tile of post_cov into SMEM (L2 hit),
// then one elected thread issues 64 cp.async.bulk SMEM->GMEM stores
// (zeros buffer as source for masked-off measurements).
__global__ void __launch_bounds__(256, 1)
k_covbcast_tma(const int* __restrict__ mask, float* __restrict__ out) {
    __shared__ __align__(128) float4 sdat[CTILE_B / 16];
    __shared__ __align__(128) float4 szero[CTILE_B / 16];

    int tile = blockIdx.x;
    const float4* src =
        reinterpret_cast<const float4*>(
            reinterpret_cast<const char*>(g_postcov4) + (size_t)tile * CTILE_B);
    const float4 z = make_float4(0.f, 0.f, 0.f, 0.f);
    for (int i = threadIdx.x; i < CTILE_B / 16; i += blockDim.x) {
        sdat[i] = __ldg(&src[i]);
        szero[i] = z;
    }
    __syncthreads();
    asm volatile("fence.proxy.async.shared::cta;" ::: "memory");

    if (threadIdx.x == 0) {
        // convert SMEM pointers to 32-bit shared addresses
        uint32_t s_dat, s_zero;
        asm("{ .reg .u64 t; cvta.to.shared.u64 t, %1; cvt.u32.u64 %0, t; }"
            : "=r"(s_dat) : "l"(sdat));
        asm("{ .reg .u64 t; cvta.to.shared.u64 t, %1; cvt.u32.u64 %0, t; }"
            : "=r"(s_zero) : "l"(szero));

        char* base = reinterpret_cast<char*>(out) + (size_t)COV_OFF * 4 +
                     (size_t)tile * CTILE_B;
#pragma unroll 8
        for (int m = 0; m < NMEAS; m++) {
            uint32_t s = (mask[m] != 0) ? s_dat : s_zero;
            void* dst = base + (size_t)m * COV_TABLE_B;
            asm volatile(
                "cp.async.bulk.global.shared::cta.bulk_group [%0], [%1], %2;"
                :: "l"(dst), "r"(s), "r"((uint32_t)CTILE_B) : "memory");
        }
        asm volatile("cp.async.bulk.commit_group;" ::: "memory");
        asm volatile("cp.async.bulk.wait_group 0;" ::: "memory");
    }
}

// ---------------- launch ----------------
extern "C" void kernel_launch(void* const* d_in, const int* in_sizes, int n_in,
                              void* d_out, int out_size) {
    const float* means = (const float*)d_in[0];
    const float* wts   = (const float*)d_in[1];
    const float* meas  = (const float*)d_in[2];
    const float* Rm    = (const float*)d_in[3];
    const int*   mask  = (const int*)d_in[4];
    float* out = (float*)d_out;

    k_cov_partial<<<NPART, 256>>>(means);
    k_cov_final<<<1, 32>>>();
    k_pern<<<(NCOMP + 127) / 128, 128>>>(means, wts, Rm);
    dim3 gu((NCOMP + 255) / 256, MSPLIT);
    k_update<<<gu, 256>>>(means, meas, mask, out);
    k_lse<<<NMEAS, 1024>>>();
    k_weights<<<(NMEAS * NCOMP + 255) / 256, 256>>>(mask, out);
    k_covbcast_tma<<<CTILES, 256>>>(mask, out);
}

// round 6
// speedup vs baseline: 1.0891x; 1.0891x over previous
#include <cuda_runtime.h>
#include <math.h>

#define NCOMP 20000
#define NMEAS 64
#define SDIM 6
#define MDIM 3
#define NPART 128
#define LOG2PI 1.8378770664093453f
#define PD_C 0.98f
#define CLUTTER_C 1e-4f

// Output layout (concatenated, float32):
//   posterior_ensemble  [64,20000,6]   offset 0
//   normalized_weights  [64,20000]     offset 7,680,000
//   posterior_covs      [64,20000,6,6] offset 8,960,000
#define ENS_OFF 0
#define W_OFF   (NMEAS * NCOMP * SDIM)
#define COV_OFF (W_OFF + NMEAS * NCOMP)

// ---------------- device scratch ----------------
__device__ double g_part[NPART * 27];
__device__ float  g_P[36];
__device__ float  g_ybar[NCOMP * 3];
__device__ float  g_K[NCOMP * 18];
__device__ float  g_Sinv[NCOMP * 6];
__device__ float  g_c0[NCOMP];
__device__ float4 g_postcov4[NCOMP * 9];
__device__ float  g_terms[NMEAS * NCOMP];
__device__ float  g_logden[NMEAS];

// ---------------- kernel 1a: partial sums for empirical covariance --------
__global__ void k_cov_partial(const float* __restrict__ means) {
    double v[27];
#pragma unroll
    for (int k = 0; k < 27; k++) v[k] = 0.0;

    for (int r = blockIdx.x * blockDim.x + threadIdx.x; r < NCOMP;
         r += gridDim.x * blockDim.x) {
        float x[6];
#pragma unroll
        for (int i = 0; i < 6; i++) x[i] = means[r * 6 + i];
#pragma unroll
        for (int i = 0; i < 6; i++) v[i] += (double)x[i];
        int idx = 6;
#pragma unroll
        for (int i = 0; i < 6; i++)
#pragma unroll
            for (int j = i; j < 6; j++)
                v[idx++] += (double)x[i] * (double)x[j];
    }

    int lane = threadIdx.x & 31;
    int warp = threadIdx.x >> 5;
    __shared__ double sh[8][27];
#pragma unroll
    for (int k = 0; k < 27; k++) {
        double s = v[k];
#pragma unroll
        for (int off = 16; off > 0; off >>= 1)
            s += __shfl_down_sync(0xffffffffu, s, off);
        if (lane == 0) sh[warp][k] = s;
    }
    __syncthreads();
    if (threadIdx.x < 27) {
        double s = 0.0;
#pragma unroll
        for (int w = 0; w < 8; w++) s += sh[w][threadIdx.x];
        g_part[blockIdx.x * 27 + threadIdx.x] = s;
    }
}

// ---------------- kernel 1b: finalize P ----------------
__global__ void k_cov_final() {
    __shared__ double acc[27];
    int k = threadIdx.x;
    if (k < 27) {
        double a = 0.0;
        for (int b = 0; b < NPART; b++) a += g_part[b * 27 + k];
        acc[k] = a;
    }
    __syncthreads();
    if (threadIdx.x == 0) {
        double mean[6];
        for (int i = 0; i < 6; i++) mean[i] = acc[i] / (double)NCOMP;
        double cov[6][6];
        int idx = 6;
        for (int i = 0; i < 6; i++)
            for (int j = i; j < 6; j++) {
                double c = (acc[idx] - (double)NCOMP * mean[i] * mean[j]) /
                           (double)(NCOMP - 1);
                cov[i][j] = c;
                cov[j][i] = c;
                idx++;
            }
        double bw = pow(4.0 / ((double)NCOMP * (SDIM + 2)), 2.0 / (SDIM + 4));
        for (int i = 0; i < 6; i++)
            for (int j = 0; j < 6; j++) {
                double d = (double)(i - j);
                double loc = exp(-(d * d) / (2.0 * 3.0 * 3.0));
                g_P[i * 6 + j] = (float)(bw * cov[i][j] * loc);
            }
    }
}

// ---------------- kernel 2: per-component linearization ----------------
__global__ void k_pern(const float* __restrict__ means,
                       const float* __restrict__ wts,
                       const float* __restrict__ Rm) {
    __shared__ float Ps[36];
    __shared__ float Rs[9];
    int tid = threadIdx.x;
    if (tid < 36) Ps[tid] = g_P[tid];
    if (tid < 9)  Rs[tid] = Rm[tid];
    __syncthreads();

    int n = blockIdx.x * blockDim.x + tid;
    if (n >= NCOMP) return;

    float mu[6];
#pragma unroll
    for (int i = 0; i < 6; i++) mu[i] = means[n * 6 + i];
    float x = mu[0], y = mu[1], z = mu[2];

    float rxy2 = x * x + y * y;
    float rho2 = rxy2 + z * z;
    float rho  = sqrtf(rho2);
    float rxy  = sqrtf(rxy2);

    float yb0 = rho;
    float yb1 = atan2f(y, x);
    float yb2 = asinf(z / rho);

    float H[3][3];
    float irho = 1.0f / rho;
    H[0][0] = x * irho; H[0][1] = y * irho; H[0][2] = z * irho;
    float irxy2 = 1.0f / rxy2;
    H[1][0] = -y * irxy2; H[1][1] = x * irxy2; H[1][2] = 0.0f;
    float den = 1.0f / (rho2 * rxy);
    H[2][0] = -x * z * den; H[2][1] = -y * z * den; H[2][2] = rxy / rho2;

    float PHt[6][3];
#pragma unroll
    for (int i = 0; i < 6; i++)
#pragma unroll
        for (int k = 0; k < 3; k++)
            PHt[i][k] = Ps[i * 6 + 0] * H[k][0] + Ps[i * 6 + 1] * H[k][1] +
                        Ps[i * 6 + 2] * H[k][2];

    float Sf[3][3];
#pragma unroll
    for (int k = 0; k < 3; k++)
#pragma unroll
        for (int l = 0; l < 3; l++)
            Sf[k][l] = H[k][0] * PHt[0][l] + H[k][1] * PHt[1][l] +
                       H[k][2] * PHt[2][l] + Rs[k * 3 + l];

    double d00 = Sf[0][0], d01 = 0.5 * ((double)Sf[0][1] + Sf[1][0]);
    double d02 = 0.5 * ((double)Sf[0][2] + Sf[2][0]);
    double d11 = Sf[1][1], d12 = 0.5 * ((double)Sf[1][2] + Sf[2][1]);
    double d22 = Sf[2][2];
    double c00 = d11 * d22 - d12 * d12;
    double c01 = d02 * d12 - d01 * d22;
    double c02 = d01 * d12 - d02 * d11;
    double det = d00 * c00 + d01 * c01 + d02 * c02;
    double idet = 1.0 / det;
    float i00 = (float)(c00 * idet);
    float i01 = (float)(c01 * idet);
    float i02 = (float)(c02 * idet);
    float i11 = (float)((d00 * d22 - d02 * d02) * idet);
    float i12 = (float)((d01 * d02 - d00 * d12) * idet);
    float i22 = (float)((d00 * d11 - d01 * d01) * idet);
    float logdet = logf((float)det);

    float K[6][3];
#pragma unroll
    for (int i = 0; i < 6; i++) {
        K[i][0] = PHt[i][0] * i00 + PHt[i][1] * i01 + PHt[i][2] * i02;
        K[i][1] = PHt[i][0] * i01 + PHt[i][1] * i11 + PHt[i][2] * i12;
        K[i][2] = PHt[i][0] * i02 + PHt[i][1] * i12 + PHt[i][2] * i22;
    }

    float KH[6][3];
#pragma unroll
    for (int i = 0; i < 6; i++)
#pragma unroll
        for (int j = 0; j < 3; j++)
            KH[i][j] = K[i][0] * H[0][j] + K[i][1] * H[1][j] + K[i][2] * H[2][j];

    float* pc = reinterpret_cast<float*>(g_postcov4);
#pragma unroll
    for (int i = 0; i < 6; i++)
#pragma unroll
        for (int j = 0; j < 6; j++) {
            float v = Ps[i * 6 + j] -
                      (KH[i][0] * Ps[0 * 6 + j] + KH[i][1] * Ps[1 * 6 + j] +
                       KH[i][2] * Ps[2 * 6 + j]);
            pc[n * 36 + i * 6 + j] = v;
        }

    g_ybar[n * 3 + 0] = yb0;
    g_ybar[n * 3 + 1] = yb1;
    g_ybar[n * 3 + 2] = yb2;
#pragma unroll
    for (int i = 0; i < 6; i++) {
        g_K[n * 18 + i * 3 + 0] = K[i][0];
        g_K[n * 18 + i * 3 + 1] = K[i][1];
        g_K[n * 18 + i * 3 + 2] = K[i][2];
    }
    g_Sinv[n * 6 + 0] = i00; g_Sinv[n * 6 + 1] = i01; g_Sinv[n * 6 + 2] = i02;
    g_Sinv[n * 6 + 3] = i11; g_Sinv[n * 6 + 4] = i12; g_Sinv[n * 6 + 5] = i22;
    g_c0[n] = logf(PD_C) + logf(wts[n]) - 0.5f * (logdet + 3.0f * LOG2PI);
}

// ---------------- kernel 3: per (m,n) update; m split across blockIdx.y ---
#define MSPLIT 8
#define MCHUNK (NMEAS / MSPLIT)    // 8
__global__ void k_update(const float* __restrict__ means,
                         const float* __restrict__ meas,
                         const int* __restrict__ mask,
                         float* __restrict__ out) {
    __shared__ float zm[MCHUNK * 3];
    __shared__ int mk[MCHUNK];
    int tid = threadIdx.x;
    int m0 = blockIdx.y * MCHUNK;
    if (tid < MCHUNK * 3) zm[tid] = meas[m0 * 3 + tid];
    if (tid < MCHUNK)     mk[tid] = mask[m0 + tid];
    __syncthreads();

    int n = blockIdx.x * blockDim.x + tid;
    if (n >= NCOMP) return;

    float mu[6];
#pragma unroll
    for (int i = 0; i < 6; i++) mu[i] = means[n * 6 + i];
    float yb0 = g_ybar[n * 3 + 0];
    float yb1 = g_ybar[n * 3 + 1];
    float yb2 = g_ybar[n * 3 + 2];
    float K[18];
#pragma unroll
    for (int i = 0; i < 18; i++) K[i] = g_K[n * 18 + i];
    float s00 = g_Sinv[n * 6 + 0], s01 = g_Sinv[n * 6 + 1],
          s02 = g_Sinv[n * 6 + 2], s11 = g_Sinv[n * 6 + 3],
          s12 = g_Sinv[n * 6 + 4], s22 = g_Sinv[n * 6 + 5];
    float c0 = g_c0[n];

#pragma unroll
    for (int mm = 0; mm < MCHUNK; mm++) {
        int m = m0 + mm;
        float r0 = yb0 - zm[mm * 3 + 0];
        float r1 = yb1 - zm[mm * 3 + 1];
        float r2 = yb2 - zm[mm * 3 + 2];
        float maha = s00 * r0 * r0 + s11 * r1 * r1 + s22 * r2 * r2 +
                     2.0f * (s01 * r0 * r1 + s02 * r0 * r2 + s12 * r1 * r2);
        g_terms[m * NCOMP + n] = c0 - 0.5f * maha;

        bool on = (mk[mm] != 0);
        float p0 = 0.f, p1 = 0.f, p2 = 0.f, p3 = 0.f, p4 = 0.f, p5 = 0.f;
        if (on) {
            p0 = mu[0] - (K[0]  * r0 + K[1]  * r1 + K[2]  * r2);
            p1 = mu[1] - (K[3]  * r0 + K[4]  * r1 + K[5]  * r2);
            p2 = mu[2] - (K[6]  * r0 + K[7]  * r1 + K[8]  * r2);
            p3 = mu[3] - (K[9]  * r0 + K[10] * r1 + K[11] * r2);
            p4 = mu[4] - (K[12] * r0 + K[13] * r1 + K[14] * r2);
            p5 = mu[5] - (K[15] * r0 + K[16] * r1 + K[17] * r2);
        }
        float2* dst = reinterpret_cast<float2*>(out + ENS_OFF +
                                                (size_t)(m * NCOMP + n) * 6);
        __stcs(&dst[0], make_float2(p0, p1));
        __stcs(&dst[1], make_float2(p2, p3));
        __stcs(&dst[2], make_float2(p4, p5));
    }
}

// ---------------- kernel 4: per-measurement logsumexp ----------------
__global__ void k_lse() {
    int m = blockIdx.x;
    int tid = threadIdx.x;
    int lane = tid & 31, warp = tid >> 5;
    __shared__ float sh[32];

    float mx = -3.4e38f;
    for (int n = tid; n < NCOMP; n += 1024)
        mx = fmaxf(mx, g_terms[m * NCOMP + n]);
#pragma unroll
    for (int off = 16; off > 0; off >>= 1)
        mx = fmaxf(mx, __shfl_down_sync(0xffffffffu, mx, off));
    if (lane == 0) sh[warp] = mx;
    __syncthreads();
    if (warp == 0) {
        float v = sh[lane];
#pragma unroll
        for (int off = 16; off > 0; off >>= 1)
            v = fmaxf(v, __shfl_down_sync(0xffffffffu, v, off));
        if (lane == 0) sh[0] = v;
    }
    __syncthreads();
    float bm = sh[0];
    __syncthreads();

    float sum = 0.0f;
    for (int n = tid; n < NCOMP; n += 1024)
        sum += expf(g_terms[m * NCOMP + n] - bm);
#pragma unroll
    for (int off = 16; off > 0; off >>= 1)
        sum += __shfl_down_sync(0xffffffffu, sum, off);
    if (lane == 0) sh[warp] = sum;
    __syncthreads();
    if (warp == 0) {
        float v = sh[lane];
#pragma unroll
        for (int off = 16; off > 0; off >>= 1)
            v += __shfl_down_sync(0xffffffffu, v, off);
        if (lane == 0) {
            float lse = bm + logf(v);
            float a = logf(CLUTTER_C);
            float hi = fmaxf(a, lse), lo = fminf(a, lse);
            g_logden[m] = hi + log1pf(expf(lo - hi));
        }
    }
}

// ---------------- kernel 5: normalized weights ----------------
__global__ void k_weights(const int* __restrict__ mask,
                          float* __restrict__ out) {
    int i = blockIdx.x * blockDim.x + threadIdx.x;
    if (i >= NMEAS * NCOMP) return;
    int m = i / NCOMP;
    float w = (mask[m] != 0) ? expf(g_terms[i] - g_logden[m]) : 0.0f;
    __stwt(out + W_OFF + i, w);
}

// ---------------- kernel 6: covariance broadcast (write-through) ----------
// 2D grid: blockIdx.y selects a group of MGRP measurements; each thread
// loads one float4 of post_cov (L2-resident) and streams MGRP write-through
// stores (st.global.wt) so the 184 MB output stream does not thrash L2.
#define MGRP 4
#define MGROUPS (NMEAS / MGRP)   // 16
__global__ void k_covbcast(const int* __restrict__ mask,
                           float* __restrict__ out) {
    __shared__ int mk[MGRP];
    int m0 = blockIdx.y * MGRP;
    if (threadIdx.x < MGRP) mk[threadIdx.x] = mask[m0 + threadIdx.x];
    __syncthreads();

    int idx = blockIdx.x * blockDim.x + threadIdx.x;
    if (idx >= NCOMP * 9) return;

    float4 v = __ldg(&g_postcov4[idx]);
    const float4 z = make_float4(0.f, 0.f, 0.f, 0.f);
    float4* dst = reinterpret_cast<float4*>(out + COV_OFF);
#pragma unroll
    for (int k = 0; k < MGRP; k++) {
        int m = m0 + k;
        float4 w = (mk[k] != 0) ? v : z;
        __stwt(&dst[(size_t)m * (NCOMP * 9) + idx], w);
    }
}

// ---------------- launch ----------------
extern "C" void kernel_launch(void* const* d_in, const int* in_sizes, int n_in,
                              void* d_out, int out_size) {
    const float* means = (const float*)d_in[0];
    const float* wts   = (const float*)d_in[1];
    const float* meas  = (const float*)d_in[2];
    const float* Rm    = (const float*)d_in[3];
    const int*   mask  = (const int*)d_in[4];
    float* out = (float*)d_out;

    k_cov_partial<<<NPART, 256>>>(means);
    k_cov_final<<<1, 32>>>();
    k_pern<<<(NCOMP + 127) / 128, 128>>>(means, wts, Rm);
    dim3 gu((NCOMP + 255) / 256, MSPLIT);
    k_update<<<gu, 256>>>(means, meas, mask, out);
    k_lse<<<NMEAS, 1024>>>();
    k_weights<<<(NMEAS * NCOMP + 255) / 256, 256>>>(mask, out);
    dim3 gc((NCOMP * 9 + 255) / 256, MGROUPS);
    k_covbcast<<<gc, 256>>>(mask, out);
}

// round 7
// speedup vs baseline: 1.1839x; 1.0870x over previous
#include <cuda_runtime.h>
#include <math.h>

#define NCOMP 20000
#define NMEAS 64
#define SDIM 6
#define MDIM 3
#define NPART 128
#define LOG2PI 1.8378770664093453f
#define PD_C 0.98f
#define CLUTTER_C 1e-4f

// Output layout (concatenated, float32):
//   posterior_ensemble  [64,20000,6]   offset 0
//   normalized_weights  [64,20000]     offset 7,680,000
//   posterior_covs      [64,20000,6,6] offset 8,960,000
#define ENS_OFF 0
#define W_OFF   (NMEAS * NCOMP * SDIM)
#define COV_OFF (W_OFF + NMEAS * NCOMP)

// ---------------- device scratch ----------------
__device__ double g_part[NPART * 27];
__device__ float  g_P[36];
__device__ float  g_ybar[NCOMP * 3];
__device__ float  g_K[NCOMP * 18];
__device__ float  g_Sinv[NCOMP * 6];
__device__ float  g_c0[NCOMP];
__device__ float4 g_postcov4[NCOMP * 9];
__device__ float  g_terms[NMEAS * NCOMP];
__device__ float  g_logden[NMEAS];

// ---------------- kernel 1a: partial sums for empirical covariance --------
__global__ void k_cov_partial(const float* __restrict__ means) {
    double v[27];
#pragma unroll
    for (int k = 0; k < 27; k++) v[k] = 0.0;

    for (int r = blockIdx.x * blockDim.x + threadIdx.x; r < NCOMP;
         r += gridDim.x * blockDim.x) {
        float x[6];
#pragma unroll
        for (int i = 0; i < 6; i++) x[i] = means[r * 6 + i];
#pragma unroll
        for (int i = 0; i < 6; i++) v[i] += (double)x[i];
        int idx = 6;
#pragma unroll
        for (int i = 0; i < 6; i++)
#pragma unroll
            for (int j = i; j < 6; j++)
                v[idx++] += (double)x[i] * (double)x[j];
    }

    int lane = threadIdx.x & 31;
    int warp = threadIdx.x >> 5;
    __shared__ double sh[8][27];
#pragma unroll
    for (int k = 0; k < 27; k++) {
        double s = v[k];
#pragma unroll
        for (int off = 16; off > 0; off >>= 1)
            s += __shfl_down_sync(0xffffffffu, s, off);
        if (lane == 0) sh[warp][k] = s;
    }
    __syncthreads();
    if (threadIdx.x < 27) {
        double s = 0.0;
#pragma unroll
        for (int w = 0; w < 8; w++) s += sh[w][threadIdx.x];
        g_part[blockIdx.x * 27 + threadIdx.x] = s;
    }
}

// ---------------- kernel 1b: finalize P ----------------
__global__ void k_cov_final() {
    __shared__ double acc[27];
    int k = threadIdx.x;
    if (k < 27) {
        double a = 0.0;
        for (int b = 0; b < NPART; b++) a += g_part[b * 27 + k];
        acc[k] = a;
    }
    __syncthreads();
    if (threadIdx.x == 0) {
        double mean[6];
        for (int i = 0; i < 6; i++) mean[i] = acc[i] / (double)NCOMP;
        double cov[6][6];
        int idx = 6;
        for (int i = 0; i < 6; i++)
            for (int j = i; j < 6; j++) {
                double c = (acc[idx] - (double)NCOMP * mean[i] * mean[j]) /
                           (double)(NCOMP - 1);
                cov[i][j] = c;
                cov[j][i] = c;
                idx++;
            }
        double bw = pow(4.0 / ((double)NCOMP * (SDIM + 2)), 2.0 / (SDIM + 4));
        for (int i = 0; i < 6; i++)
            for (int j = 0; j < 6; j++) {
                double d = (double)(i - j);
                double loc = exp(-(d * d) / (2.0 * 3.0 * 3.0));
                g_P[i * 6 + j] = (float)(bw * cov[i][j] * loc);
            }
    }
}

// ---------------- kernel 2: per-component linearization ----------------
__global__ void k_pern(const float* __restrict__ means,
                       const float* __restrict__ wts,
                       const float* __restrict__ Rm) {
    __shared__ float Ps[36];
    __shared__ float Rs[9];
    int tid = threadIdx.x;
    if (tid < 36) Ps[tid] = g_P[tid];
    if (tid < 9)  Rs[tid] = Rm[tid];
    __syncthreads();

    int n = blockIdx.x * blockDim.x + tid;
    if (n >= NCOMP) return;

    float mu[6];
#pragma unroll
    for (int i = 0; i < 6; i++) mu[i] = means[n * 6 + i];
    float x = mu[0], y = mu[1], z = mu[2];

    float rxy2 = x * x + y * y;
    float rho2 = rxy2 + z * z;
    float rho  = sqrtf(rho2);
    float rxy  = sqrtf(rxy2);

    float yb0 = rho;
    float yb1 = atan2f(y, x);
    float yb2 = asinf(z / rho);

    float H[3][3];
    float irho = 1.0f / rho;
    H[0][0] = x * irho; H[0][1] = y * irho; H[0][2] = z * irho;
    float irxy2 = 1.0f / rxy2;
    H[1][0] = -y * irxy2; H[1][1] = x * irxy2; H[1][2] = 0.0f;
    float den = 1.0f / (rho2 * rxy);
    H[2][0] = -x * z * den; H[2][1] = -y * z * den; H[2][2] = rxy / rho2;

    float PHt[6][3];
#pragma unroll
    for (int i = 0; i < 6; i++)
#pragma unroll
        for (int k = 0; k < 3; k++)
            PHt[i][k] = Ps[i * 6 + 0] * H[k][0] + Ps[i * 6 + 1] * H[k][1] +
                        Ps[i * 6 + 2] * H[k][2];

    float Sf[3][3];
#pragma unroll
    for (int k = 0; k < 3; k++)
#pragma unroll
        for (int l = 0; l < 3; l++)
            Sf[k][l] = H[k][0] * PHt[0][l] + H[k][1] * PHt[1][l] +
                       H[k][2] * PHt[2][l] + Rs[k * 3 + l];

    double d00 = Sf[0][0], d01 = 0.5 * ((double)Sf[0][1] + Sf[1][0]);
    double d02 = 0.5 * ((double)Sf[0][2] + Sf[2][0]);
    double d11 = Sf[1][1], d12 = 0.5 * ((double)Sf[1][2] + Sf[2][1]);
    double d22 = Sf[2][2];
    double c00 = d11 * d22 - d12 * d12;
    double c01 = d02 * d12 - d01 * d22;
    double c02 = d01 * d12 - d02 * d11;
    double det = d00 * c00 + d01 * c01 + d02 * c02;
    double idet = 1.0 / det;
    float i00 = (float)(c00 * idet);
    float i01 = (float)(c01 * idet);
    float i02 = (float)(c02 * idet);
    float i11 = (float)((d00 * d22 - d02 * d02) * idet);
    float i12 = (float)((d01 * d02 - d00 * d12) * idet);
    float i22 = (float)((d00 * d11 - d01 * d01) * idet);
    float logdet = logf((float)det);

    float K[6][3];
#pragma unroll
    for (int i = 0; i < 6; i++) {
        K[i][0] = PHt[i][0] * i00 + PHt[i][1] * i01 + PHt[i][2] * i02;
        K[i][1] = PHt[i][0] * i01 + PHt[i][1] * i11 + PHt[i][2] * i12;
        K[i][2] = PHt[i][0] * i02 + PHt[i][1] * i12 + PHt[i][2] * i22;
    }

    float KH[6][3];
#pragma unroll
    for (int i = 0; i < 6; i++)
#pragma unroll
        for (int j = 0; j < 3; j++)
            KH[i][j] = K[i][0] * H[0][j] + K[i][1] * H[1][j] + K[i][2] * H[2][j];

    float* pc = reinterpret_cast<float*>(g_postcov4);
#pragma unroll
    for (int i = 0; i < 6; i++)
#pragma unroll
        for (int j = 0; j < 6; j++) {
            float v = Ps[i * 6 + j] -
                      (KH[i][0] * Ps[0 * 6 + j] + KH[i][1] * Ps[1 * 6 + j] +
                       KH[i][2] * Ps[2 * 6 + j]);
            pc[n * 36 + i * 6 + j] = v;
        }

    g_ybar[n * 3 + 0] = yb0;
    g_ybar[n * 3 + 1] = yb1;
    g_ybar[n * 3 + 2] = yb2;
#pragma unroll
    for (int i = 0; i < 6; i++) {
        g_K[n * 18 + i * 3 + 0] = K[i][0];
        g_K[n * 18 + i * 3 + 1] = K[i][1];
        g_K[n * 18 + i * 3 + 2] = K[i][2];
    }
    g_Sinv[n * 6 + 0] = i00; g_Sinv[n * 6 + 1] = i01; g_Sinv[n * 6 + 2] = i02;
    g_Sinv[n * 6 + 3] = i11; g_Sinv[n * 6 + 4] = i12; g_Sinv[n * 6 + 5] = i22;
    g_c0[n] = logf(PD_C) + logf(wts[n]) - 0.5f * (logdet + 3.0f * LOG2PI);
}

// ---------------- kernel 3: per (m,n) update; m split across blockIdx.y ---
#define MSPLIT 8
#define MCHUNK (NMEAS / MSPLIT)    // 8
__global__ void k_update(const float* __restrict__ means,
                         const float* __restrict__ meas,
                         const int* __restrict__ mask,
                         float* __restrict__ out) {
    __shared__ float zm[MCHUNK * 3];
    __shared__ int mk[MCHUNK];
    int tid = threadIdx.x;
    int m0 = blockIdx.y * MCHUNK;
    if (tid < MCHUNK * 3) zm[tid] = meas[m0 * 3 + tid];
    if (tid < MCHUNK)     mk[tid] = mask[m0 + tid];
    __syncthreads();

    int n = blockIdx.x * blockDim.x + tid;
    if (n >= NCOMP) return;

    float mu[6];
#pragma unroll
    for (int i = 0; i < 6; i++) mu[i] = means[n * 6 + i];
    float yb0 = g_ybar[n * 3 + 0];
    float yb1 = g_ybar[n * 3 + 1];
    float yb2 = g_ybar[n * 3 + 2];
    float K[18];
#pragma unroll
    for (int i = 0; i < 18; i++) K[i] = g_K[n * 18 + i];
    float s00 = g_Sinv[n * 6 + 0], s01 = g_Sinv[n * 6 + 1],
          s02 = g_Sinv[n * 6 + 2], s11 = g_Sinv[n * 6 + 3],
          s12 = g_Sinv[n * 6 + 4], s22 = g_Sinv[n * 6 + 5];
    float c0 = g_c0[n];

#pragma unroll
    for (int mm = 0; mm < MCHUNK; mm++) {
        int m = m0 + mm;
        float r0 = yb0 - zm[mm * 3 + 0];
        float r1 = yb1 - zm[mm * 3 + 1];
        float r2 = yb2 - zm[mm * 3 + 2];
        float maha = s00 * r0 * r0 + s11 * r1 * r1 + s22 * r2 * r2 +
                     2.0f * (s01 * r0 * r1 + s02 * r0 * r2 + s12 * r1 * r2);
        g_terms[m * NCOMP + n] = c0 - 0.5f * maha;

        bool on = (mk[mm] != 0);
        float p0 = 0.f, p1 = 0.f, p2 = 0.f, p3 = 0.f, p4 = 0.f, p5 = 0.f;
        if (on) {
            p0 = mu[0] - (K[0]  * r0 + K[1]  * r1 + K[2]  * r2);
            p1 = mu[1] - (K[3]  * r0 + K[4]  * r1 + K[5]  * r2);
            p2 = mu[2] - (K[6]  * r0 + K[7]  * r1 + K[8]  * r2);
            p3 = mu[3] - (K[9]  * r0 + K[10] * r1 + K[11] * r2);
            p4 = mu[4] - (K[12] * r0 + K[13] * r1 + K[14] * r2);
            p5 = mu[5] - (K[15] * r0 + K[16] * r1 + K[17] * r2);
        }
        float2* dst = reinterpret_cast<float2*>(out + ENS_OFF +
                                                (size_t)(m * NCOMP + n) * 6);
        __stcs(&dst[0], make_float2(p0, p1));
        __stcs(&dst[1], make_float2(p2, p3));
        __stcs(&dst[2], make_float2(p4, p5));
    }
}

// ---------------- kernel 4: per-measurement logsumexp ----------------
__global__ void k_lse() {
    int m = blockIdx.x;
    int tid = threadIdx.x;
    int lane = tid & 31, warp = tid >> 5;
    __shared__ float sh[32];

    float mx = -3.4e38f;
    for (int n = tid; n < NCOMP; n += 1024)
        mx = fmaxf(mx, g_terms[m * NCOMP + n]);
#pragma unroll
    for (int off = 16; off > 0; off >>= 1)
        mx = fmaxf(mx, __shfl_down_sync(0xffffffffu, mx, off));
    if (lane == 0) sh[warp] = mx;
    __syncthreads();
    if (warp == 0) {
        float v = sh[lane];
#pragma unroll
        for (int off = 16; off > 0; off >>= 1)
            v = fmaxf(v, __shfl_down_sync(0xffffffffu, v, off));
        if (lane == 0) sh[0] = v;
    }
    __syncthreads();
    float bm = sh[0];
    __syncthreads();

    float sum = 0.0f;
    for (int n = tid; n < NCOMP; n += 1024)
        sum += expf(g_terms[m * NCOMP + n] - bm);
#pragma unroll
    for (int off = 16; off > 0; off >>= 1)
        sum += __shfl_down_sync(0xffffffffu, sum, off);
    if (lane == 0) sh[warp] = sum;
    __syncthreads();
    if (warp == 0) {
        float v = sh[lane];
#pragma unroll
        for (int off = 16; off > 0; off >>= 1)
            v += __shfl_down_sync(0xffffffffu, v, off);
        if (lane == 0) {
            float lse = bm + logf(v);
            float a = logf(CLUTTER_C);
            float hi = fmaxf(a, lse), lo = fminf(a, lse);
            g_logden[m] = hi + log1pf(expf(lo - hi));
        }
    }
}

// ---------------- kernel 5: normalized weights ----------------
__global__ void k_weights(const int* __restrict__ mask,
                          float* __restrict__ out) {
    int i = blockIdx.x * blockDim.x + threadIdx.x;
    if (i >= NMEAS * NCOMP) return;
    int m = i / NCOMP;
    float w = (mask[m] != 0) ? expf(g_terms[i] - g_logden[m]) : 0.0f;
    __stcs(out + W_OFF + i, w);
}

// ---------------- kernel 6: covariance broadcast (R4 best config) ---------
#define MGRP 8
#define MGROUPS (NMEAS / MGRP)   // 8
__global__ void k_covbcast(const int* __restrict__ mask,
                           float* __restrict__ out) {
    __shared__ int mk[MGRP];
    int m0 = blockIdx.y * MGRP;
    if (threadIdx.x < MGRP) mk[threadIdx.x] = mask[m0 + threadIdx.x];
    __syncthreads();

    int idx = blockIdx.x * blockDim.x + threadIdx.x;
    if (idx >= NCOMP * 9) return;

    float4 v = __ldg(&g_postcov4[idx]);
    const float4 z = make_float4(0.f, 0.f, 0.f, 0.f);
    float4* dst = reinterpret_cast<float4*>(out + COV_OFF);
#pragma unroll
    for (int k = 0; k < MGRP; k++) {
        int m = m0 + k;
        float4 w = (mk[k] != 0) ? v : z;
        __stcs(&dst[(size_t)m * (NCOMP * 9) + idx], w);
    }
}

// ---------------- launch: fork covbcast onto a side stream ----------------
static cudaStream_t g_s2 = nullptr;
static cudaEvent_t  g_evFork = nullptr, g_evJoin = nullptr;

extern "C" void kernel_launch(void* const* d_in, const int* in_sizes, int n_in,
                              void* d_out, int out_size) {
    const float* means = (const float*)d_in[0];
    const float* wts   = (const float*)d_in[1];
    const float* meas  = (const float*)d_in[2];
    const float* Rm    = (const float*)d_in[3];
    const int*   mask  = (const int*)d_in[4];
    float* out = (float*)d_out;

    if (g_s2 == nullptr) {
        cudaStreamCreateWithFlags(&g_s2, cudaStreamNonBlocking);
        cudaEventCreateWithFlags(&g_evFork, cudaEventDisableTiming);
        cudaEventCreateWithFlags(&g_evJoin, cudaEventDisableTiming);
    }

    // main (capture) stream: reductions + linearization
    k_cov_partial<<<NPART, 256>>>(means);
    k_cov_final<<<1, 32>>>();
    k_pern<<<(NCOMP + 127) / 128, 128>>>(means, wts, Rm);

    // fork: covbcast depends only on k_pern's post_cov table + mask
    cudaEventRecord(g_evFork, 0);
    cudaStreamWaitEvent(g_s2, g_evFork, 0);
    dim3 gc((NCOMP * 9 + 255) / 256, MGROUPS);
    k_covbcast<<<gc, 256, 0, g_s2>>>(mask, out);
    cudaEventRecord(g_evJoin, g_s2);

    // main stream continues with the update chain concurrently
    dim3 gu((NCOMP + 255) / 256, MSPLIT);
    k_update<<<gu, 256>>>(means, meas, mask, out);
    k_lse<<<NMEAS, 1024>>>();
    k_weights<<<(NMEAS * NCOMP + 255) / 256, 256>>>(mask, out);

    // join side branch back into the capture stream
    cudaStreamWaitEvent(0, g_evJoin, 0);
}

// round 8
// speedup vs baseline: 1.7693x; 1.4945x over previous
#include <cuda_runtime.h>
#include <math.h>

#define NCOMP 20000
#define NMEAS 64
#define SDIM 6
#define MDIM 3
#define NPART 128
#define LOG2PI 1.8378770664093453f
#define PD_C 0.98f
#define CLUTTER_C 1e-4f

#define ENS_OFF 0
#define W_OFF   (NMEAS * NCOMP * SDIM)
#define COV_OFF (W_OFF + NMEAS * NCOMP)

// ---------------- device scratch ----------------
__device__ double g_part[NPART * 27];
__device__ float  g_P[36];
__device__ float  g_ybar[NCOMP * 3];
__device__ float  g_K[NCOMP * 18];
__device__ float  g_Sinv[NCOMP * 6];
__device__ float  g_c0[NCOMP];
__device__ float4 g_postcov4[NCOMP * 9];
__device__ float  g_terms[NMEAS * NCOMP];

// ---------------- kernel 1a: partial sums for empirical covariance --------
__global__ void k_cov_partial(const float* __restrict__ means) {
    double v[27];
#pragma unroll
    for (int k = 0; k < 27; k++) v[k] = 0.0;

    for (int r = blockIdx.x * blockDim.x + threadIdx.x; r < NCOMP;
         r += gridDim.x * blockDim.x) {
        float x[6];
#pragma unroll
        for (int i = 0; i < 6; i++) x[i] = means[r * 6 + i];
#pragma unroll
        for (int i = 0; i < 6; i++) v[i] += (double)x[i];
        int idx = 6;
#pragma unroll
        for (int i = 0; i < 6; i++)
#pragma unroll
            for (int j = i; j < 6; j++)
                v[idx++] += (double)x[i] * (double)x[j];
    }

    int lane = threadIdx.x & 31;
    int warp = threadIdx.x >> 5;
    __shared__ double sh[8][27];
#pragma unroll
    for (int k = 0; k < 27; k++) {
        double s = v[k];
#pragma unroll
        for (int off = 16; off > 0; off >>= 1)
            s += __shfl_down_sync(0xffffffffu, s, off);
        if (lane == 0) sh[warp][k] = s;
    }
    __syncthreads();
    if (threadIdx.x < 27) {
        double s = 0.0;
#pragma unroll
        for (int w = 0; w < 8; w++) s += sh[w][threadIdx.x];
        g_part[blockIdx.x * 27 + threadIdx.x] = s;
    }
}

// ---------------- kernel 1b: finalize P (parallel, 36 threads) ------------
__global__ void k_cov_final() {
    int t = threadIdx.x;
    __shared__ double acc[27];
    if (t < 27) {
        double a = 0.0;
        for (int b = 0; b < NPART; b++) a += g_part[b * 27 + t];
        acc[t] = a;
    }
    __syncthreads();
    if (t >= 36) return;
    int i = t / 6, j = t % 6;
    double mi = acc[i] / (double)NCOMP;
    double mj = acc[j] / (double)NCOMP;
    int ii = (i < j) ? i : j;
    int jj = (i < j) ? j : i;
    int tri = 6 + (ii * (13 - ii)) / 2 + (jj - ii);   // packed upper-tri index
    double c = (acc[tri] - (double)NCOMP * mi * mj) / (double)(NCOMP - 1);
    double bw = pow(4.0 / ((double)NCOMP * (SDIM + 2)), 2.0 / (SDIM + 4));
    double d = (double)(i - j);
    double loc = exp(-(d * d) / (2.0 * 3.0 * 3.0));
    g_P[i * 6 + j] = (float)(bw * c * loc);
}

// ---------------- kernel 2: per-component linearization ----------------
__global__ void k_pern(const float* __restrict__ means,
                       const float* __restrict__ wts,
                       const float* __restrict__ Rm) {
    __shared__ float Ps[36];
    __shared__ float Rs[9];
    int tid = threadIdx.x;
    if (tid < 36) Ps[tid] = g_P[tid];
    if (tid < 9)  Rs[tid] = Rm[tid];
    __syncthreads();

    int n = blockIdx.x * blockDim.x + tid;
    if (n >= NCOMP) return;

    float mu[6];
#pragma unroll
    for (int i = 0; i < 6; i++) mu[i] = means[n * 6 + i];
    float x = mu[0], y = mu[1], z = mu[2];

    float rxy2 = x * x + y * y;
    float rho2 = rxy2 + z * z;
    float rho  = sqrtf(rho2);
    float rxy  = sqrtf(rxy2);

    float yb0 = rho;
    float yb1 = atan2f(y, x);
    float yb2 = asinf(z / rho);

    float H[3][3];
    float irho = 1.0f / rho;
    H[0][0] = x * irho; H[0][1] = y * irho; H[0][2] = z * irho;
    float irxy2 = 1.0f / rxy2;
    H[1][0] = -y * irxy2; H[1][1] = x * irxy2; H[1][2] = 0.0f;
    float den = 1.0f / (rho2 * rxy);
    H[2][0] = -x * z * den; H[2][1] = -y * z * den; H[2][2] = rxy / rho2;

    float PHt[6][3];
#pragma unroll
    for (int i = 0; i < 6; i++)
#pragma unroll
        for (int k = 0; k < 3; k++)
            PHt[i][k] = Ps[i * 6 + 0] * H[k][0] + Ps[i * 6 + 1] * H[k][1] +
                        Ps[i * 6 + 2] * H[k][2];

    float Sf[3][3];
#pragma unroll
    for (int k = 0; k < 3; k++)
#pragma unroll
        for (int l = 0; l < 3; l++)
            Sf[k][l] = H[k][0] * PHt[0][l] + H[k][1] * PHt[1][l] +
                       H[k][2] * PHt[2][l] + Rs[k * 3 + l];

    double d00 = Sf[0][0], d01 = 0.5 * ((double)Sf[0][1] + Sf[1][0]);
    double d02 = 0.5 * ((double)Sf[0][2] + Sf[2][0]);
    double d11 = Sf[1][1], d12 = 0.5 * ((double)Sf[1][2] + Sf[2][1]);
    double d22 = Sf[2][2];
    double c00 = d11 * d22 - d12 * d12;
    double c01 = d02 * d12 - d01 * d22;
    double c02 = d01 * d12 - d02 * d11;
    double det = d00 * c00 + d01 * c01 + d02 * c02;
    double idet = 1.0 / det;
    float i00 = (float)(c00 * idet);
    float i01 = (float)(c01 * idet);
    float i02 = (float)(c02 * idet);
    float i11 = (float)((d00 * d22 - d02 * d02) * idet);
    float i12 = (float)((d01 * d02 - d00 * d12) * idet);
    float i22 = (float)((d00 * d11 - d01 * d01) * idet);
    float logdet = logf((float)det);

    float K[6][3];
#pragma unroll
    for (int i = 0; i < 6; i++) {
        K[i][0] = PHt[i][0] * i00 + PHt[i][1] * i01 + PHt[i][2] * i02;
        K[i][1] = PHt[i][0] * i01 + PHt[i][1] * i11 + PHt[i][2] * i12;
        K[i][2] = PHt[i][0] * i02 + PHt[i][1] * i12 + PHt[i][2] * i22;
    }

    float KH[6][3];
#pragma unroll
    for (int i = 0; i < 6; i++)
#pragma unroll
        for (int j = 0; j < 3; j++)
            KH[i][j] = K[i][0] * H[0][j] + K[i][1] * H[1][j] + K[i][2] * H[2][j];

    float* pc = reinterpret_cast<float*>(g_postcov4);
#pragma unroll
    for (int i = 0; i < 6; i++)
#pragma unroll
        for (int j = 0; j < 6; j++) {
            float v = Ps[i * 6 + j] -
                      (KH[i][0] * Ps[0 * 6 + j] + KH[i][1] * Ps[1 * 6 + j] +
                       KH[i][2] * Ps[2 * 6 + j]);
            pc[n * 36 + i * 6 + j] = v;
        }

    g_ybar[n * 3 + 0] = yb0;
    g_ybar[n * 3 + 1] = yb1;
    g_ybar[n * 3 + 2] = yb2;
#pragma unroll
    for (int i = 0; i < 6; i++) {
        g_K[n * 18 + i * 3 + 0] = K[i][0];
        g_K[n * 18 + i * 3 + 1] = K[i][1];
        g_K[n * 18 + i * 3 + 2] = K[i][2];
    }
    g_Sinv[n * 6 + 0] = i00; g_Sinv[n * 6 + 1] = i01; g_Sinv[n * 6 + 2] = i02;
    g_Sinv[n * 6 + 3] = i11; g_Sinv[n * 6 + 4] = i12; g_Sinv[n * 6 + 5] = i22;
    g_c0[n] = logf(PD_C) + logf(wts[n]) - 0.5f * (logdet + 3.0f * LOG2PI);
}

// ---------------- kernel 3: per (m,n) update; m split across blockIdx.y ---
#define MSPLIT 8
#define MCHUNK (NMEAS / MSPLIT)    // 8
__global__ void k_update(const float* __restrict__ means,
                         const float* __restrict__ meas,
                         const int* __restrict__ mask,
                         float* __restrict__ out) {
    __shared__ float zm[MCHUNK * 3];
    __shared__ int mk[MCHUNK];
    int tid = threadIdx.x;
    int m0 = blockIdx.y * MCHUNK;
    if (tid < MCHUNK * 3) zm[tid] = meas[m0 * 3 + tid];
    if (tid < MCHUNK)     mk[tid] = mask[m0 + tid];
    __syncthreads();

    int n = blockIdx.x * blockDim.x + tid;
    if (n >= NCOMP) return;

    float mu[6];
#pragma unroll
    for (int i = 0; i < 6; i++) mu[i] = means[n * 6 + i];
    float yb0 = g_ybar[n * 3 + 0];
    float yb1 = g_ybar[n * 3 + 1];
    float yb2 = g_ybar[n * 3 + 2];
    float K[18];
#pragma unroll
    for (int i = 0; i < 18; i++) K[i] = g_K[n * 18 + i];
    float s00 = g_Sinv[n * 6 + 0], s01 = g_Sinv[n * 6 + 1],
          s02 = g_Sinv[n * 6 + 2], s11 = g_Sinv[n * 6 + 3],
          s12 = g_Sinv[n * 6 + 4], s22 = g_Sinv[n * 6 + 5];
    float c0 = g_c0[n];

#pragma unroll
    for (int mm = 0; mm < MCHUNK; mm++) {
        int m = m0 + mm;
        float r0 = yb0 - zm[mm * 3 + 0];
        float r1 = yb1 - zm[mm * 3 + 1];
        float r2 = yb2 - zm[mm * 3 + 2];
        float maha = s00 * r0 * r0 + s11 * r1 * r1 + s22 * r2 * r2 +
                     2.0f * (s01 * r0 * r1 + s02 * r0 * r2 + s12 * r1 * r2);
        g_terms[m * NCOMP + n] = c0 - 0.5f * maha;

        bool on = (mk[mm] != 0);
        float p0 = 0.f, p1 = 0.f, p2 = 0.f, p3 = 0.f, p4 = 0.f, p5 = 0.f;
        if (on) {
            p0 = mu[0] - (K[0]  * r0 + K[1]  * r1 + K[2]  * r2);
            p1 = mu[1] - (K[3]  * r0 + K[4]  * r1 + K[5]  * r2);
            p2 = mu[2] - (K[6]  * r0 + K[7]  * r1 + K[8]  * r2);
            p3 = mu[3] - (K[9]  * r0 + K[10] * r1 + K[11] * r2);
            p4 = mu[4] - (K[12] * r0 + K[13] * r1 + K[14] * r2);
            p5 = mu[5] - (K[15] * r0 + K[16] * r1 + K[17] * r2);
        }
        float2* dst = reinterpret_cast<float2*>(out + ENS_OFF +
                                                (size_t)(m * NCOMP + n) * 6);
        __stcs(&dst[0], make_float2(p0, p1));
        __stcs(&dst[1], make_float2(p2, p3));
        __stcs(&dst[2], make_float2(p4, p5));
    }
}

// ---------------- kernel 4: fused logsumexp + weights ----------------
__global__ void k_lse_weights(const int* __restrict__ mask,
                              float* __restrict__ out) {
    int m = blockIdx.x;
    int tid = threadIdx.x;
    int lane = tid & 31, warp = tid >> 5;
    __shared__ float sh[32];
    __shared__ float s_logden;

    const float* terms = g_terms + m * NCOMP;

    float mx = -3.4e38f;
    for (int n = tid; n < NCOMP; n += 1024)
        mx = fmaxf(mx, terms[n]);
#pragma unroll
    for (int off = 16; off > 0; off >>= 1)
        mx = fmaxf(mx, __shfl_down_sync(0xffffffffu, mx, off));
    if (lane == 0) sh[warp] = mx;
    __syncthreads();
    if (warp == 0) {
        float v = sh[lane];
#pragma unroll
        for (int off = 16; off > 0; off >>= 1)
            v = fmaxf(v, __shfl_down_sync(0xffffffffu, v, off));
        if (lane == 0) sh[0] = v;
    }
    __syncthreads();
    float bm = sh[0];
    __syncthreads();

    float sum = 0.0f;
    for (int n = tid; n < NCOMP; n += 1024)
        sum += expf(terms[n] - bm);
#pragma unroll
    for (int off = 16; off > 0; off >>= 1)
        sum += __shfl_down_sync(0xffffffffu, sum, off);
    if (lane == 0) sh[warp] = sum;
    __syncthreads();
    if (warp == 0) {
        float v = sh[lane];
#pragma unroll
        for (int off = 16; off > 0; off >>= 1)
            v += __shfl_down_sync(0xffffffffu, v, off);
        if (lane == 0) {
            float lse = bm + logf(v);
            float a = logf(CLUTTER_C);
            float hi = fmaxf(a, lse), lo = fminf(a, lse);
            s_logden = hi + log1pf(expf(lo - hi));
        }
    }
    __syncthreads();

    float ld = s_logden;
    bool on = (mask[m] != 0);
    float* wout = out + W_OFF + m * NCOMP;
    for (int n = tid; n < NCOMP; n += 1024) {
        float w = on ? expf(terms[n] - ld) : 0.0f;
        __stcs(wout + n, w);
    }
}

// ---------------- kernel 5: covariance broadcast (R4 best config) ---------
#define MGRP 8
#define MGROUPS (NMEAS / MGRP)   // 8
__global__ void k_covbcast(const int* __restrict__ mask,
                           float* __restrict__ out) {
    __shared__ int mk[MGRP];
    int m0 = blockIdx.y * MGRP;
    if (threadIdx.x < MGRP) mk[threadIdx.x] = mask[m0 + threadIdx.x];
    __syncthreads();

    int idx = blockIdx.x * blockDim.x + threadIdx.x;
    if (idx >= NCOMP * 9) return;

    float4 v = __ldg(&g_postcov4[idx]);
    const float4 z = make_float4(0.f, 0.f, 0.f, 0.f);
    float4* dst = reinterpret_cast<float4*>(out + COV_OFF);
#pragma unroll
    for (int k = 0; k < MGRP; k++) {
        int m = m0 + k;
        float4 w = (mk[k] != 0) ? v : z;
        __stcs(&dst[(size_t)m * (NCOMP * 9) + idx], w);
    }
}

// ---------------- launch: fork covbcast onto a side stream ----------------
static cudaStream_t g_s2 = nullptr;
static cudaEvent_t  g_evFork = nullptr, g_evJoin = nullptr;

extern "C" void kernel_launch(void* const* d_in, const int* in_sizes, int n_in,
                              void* d_out, int out_size) {
    const float* means = (const float*)d_in[0];
    const float* wts   = (const float*)d_in[1];
    const float* meas  = (const float*)d_in[2];
    const float* Rm    = (const float*)d_in[3];
    const int*   mask  = (const int*)d_in[4];
    float* out = (float*)d_out;

    if (g_s2 == nullptr) {
        cudaStreamCreateWithFlags(&g_s2, cudaStreamNonBlocking);
        cudaEventCreateWithFlags(&g_evFork, cudaEventDisableTiming);
        cudaEventCreateWithFlags(&g_evJoin, cudaEventDisableTiming);
    }

    // main (capture) stream: reductions + linearization
    k_cov_partial<<<NPART, 256>>>(means);
    k_cov_final<<<1, 64>>>();
    k_pern<<<(NCOMP + 127) / 128, 128>>>(means, wts, Rm);

    // fork: covbcast depends only on k_pern's post_cov table + mask
    cudaEventRecord(g_evFork, 0);
    cudaStreamWaitEvent(g_s2, g_evFork, 0);
    dim3 gc((NCOMP * 9 + 255) / 256, MGROUPS);
    k_covbcast<<<gc, 256, 0, g_s2>>>(mask, out);
    cudaEventRecord(g_evJoin, g_s2);

    // main stream continues with the update chain concurrently
    dim3 gu((NCOMP + 255) / 256, MSPLIT);
    k_update<<<gu, 256>>>(means, meas, mask, out);
    k_lse_weights<<<NMEAS, 1024>>>(mask, out);

    // join side branch back into the capture stream
    cudaStreamWaitEvent(0, g_evJoin, 0);
}

// round 9
// speedup vs baseline: 2.1295x; 1.2035x over previous
#include <cuda_runtime.h>
#include <math.h>

#define NCOMP 20000
#define NMEAS 64
#define SDIM 6
#define MDIM 3
#define NPART 128
#define LOG2PI 1.8378770664093453f
#define PD_C 0.98f
#define CLUTTER_C 1e-4f

#define ENS_OFF 0
#define W_OFF   (NMEAS * NCOMP * SDIM)
#define COV_OFF (W_OFF + NMEAS * NCOMP)

// ---------------- device scratch ----------------
__device__ float  g_part[NPART * 27];   // float partials (anchored)
__device__ float  g_P[36];
__device__ float  g_ybar[NCOMP * 3];
__device__ float  g_K[NCOMP * 18];
__device__ float  g_Sinv[NCOMP * 6];
__device__ float  g_c0[NCOMP];
__device__ float4 g_postcov4[NCOMP * 9];
__device__ float  g_terms[NMEAS * NCOMP];

// ---------------- kernel 1a: anchored float partial sums ------------------
// Deviations from an anchor (row 0 of means) keep magnitudes small so
// float accumulation + tree reduction matches f32 jnp.cov accuracy.
__global__ void k_cov_partial(const float* __restrict__ means) {
    // anchor = component 0 state (broadcast load, L2/L1 cached)
    float a[6];
#pragma unroll
    for (int i = 0; i < 6; i++) a[i] = __ldg(&means[i]);

    float v[27];
#pragma unroll
    for (int k = 0; k < 27; k++) v[k] = 0.0f;

    for (int r = blockIdx.x * blockDim.x + threadIdx.x; r < NCOMP;
         r += gridDim.x * blockDim.x) {
        float d[6];
#pragma unroll
        for (int i = 0; i < 6; i++) d[i] = means[r * 6 + i] - a[i];
#pragma unroll
        for (int i = 0; i < 6; i++) v[i] += d[i];
        int idx = 6;
#pragma unroll
        for (int i = 0; i < 6; i++)
#pragma unroll
            for (int j = i; j < 6; j++)
                v[idx++] = fmaf(d[i], d[j], v[idx]);
    }

    int lane = threadIdx.x & 31;
    int warp = threadIdx.x >> 5;
    __shared__ float sh[8][27];
#pragma unroll
    for (int k = 0; k < 27; k++) {
        float s = v[k];
#pragma unroll
        for (int off = 16; off > 0; off >>= 1)
            s += __shfl_down_sync(0xffffffffu, s, off);
        if (lane == 0) sh[warp][k] = s;
    }
    __syncthreads();
    if (threadIdx.x < 27) {
        float s = 0.0f;
#pragma unroll
        for (int w = 0; w < 8; w++) s += sh[w][threadIdx.x];
        g_part[blockIdx.x * 27 + threadIdx.x] = s;
    }
}

// ---------------- kernel 1b: finalize P (parallel, 36 threads, tiny fp64) -
__global__ void k_cov_final() {
    int t = threadIdx.x;
    __shared__ double acc[27];
    if (t < 27) {
        double s = 0.0;
        for (int b = 0; b < NPART; b++) s += (double)g_part[b * 27 + t];
        acc[t] = s;
    }
    __syncthreads();
    if (t >= 36) return;
    int i = t / 6, j = t % 6;
    // anchored moments: cov = (Sdij - N*mdi*mdj)/(N-1); anchor cancels.
    double mdi = acc[i] / (double)NCOMP;
    double mdj = acc[j] / (double)NCOMP;
    int ii = (i < j) ? i : j;
    int jj = (i < j) ? j : i;
    int tri = 6 + (ii * (13 - ii)) / 2 + (jj - ii);
    double c = (acc[tri] - (double)NCOMP * mdi * mdj) / (double)(NCOMP - 1);
    double bw = pow(4.0 / ((double)NCOMP * (SDIM + 2)), 2.0 / (SDIM + 4));
    double d = (double)(i - j);
    double loc = exp(-(d * d) / (2.0 * 3.0 * 3.0));
    g_P[i * 6 + j] = (float)(bw * c * loc);
}

// ---------------- kernel 2: per-component linearization (all float) -------
__global__ void k_pern(const float* __restrict__ means,
                       const float* __restrict__ wts,
                       const float* __restrict__ Rm) {
    __shared__ float Ps[36];
    __shared__ float Rs[9];
    int tid = threadIdx.x;
    if (tid < 36) Ps[tid] = g_P[tid];
    if (tid < 9)  Rs[tid] = Rm[tid];
    __syncthreads();

    int n = blockIdx.x * blockDim.x + tid;
    if (n >= NCOMP) return;

    float mu[6];
#pragma unroll
    for (int i = 0; i < 6; i++) mu[i] = means[n * 6 + i];
    float x = mu[0], y = mu[1], z = mu[2];

    float rxy2 = x * x + y * y;
    float rho2 = rxy2 + z * z;
    float rho  = sqrtf(rho2);
    float rxy  = sqrtf(rxy2);

    float yb0 = rho;
    float yb1 = atan2f(y, x);
    float yb2 = asinf(z / rho);

    float H[3][3];
    float irho = 1.0f / rho;
    H[0][0] = x * irho; H[0][1] = y * irho; H[0][2] = z * irho;
    float irxy2 = 1.0f / rxy2;
    H[1][0] = -y * irxy2; H[1][1] = x * irxy2; H[1][2] = 0.0f;
    float den = 1.0f / (rho2 * rxy);
    H[2][0] = -x * z * den; H[2][1] = -y * z * den; H[2][2] = rxy / rho2;

    float PHt[6][3];
#pragma unroll
    for (int i = 0; i < 6; i++)
#pragma unroll
        for (int k = 0; k < 3; k++)
            PHt[i][k] = Ps[i * 6 + 0] * H[k][0] + Ps[i * 6 + 1] * H[k][1] +
                        Ps[i * 6 + 2] * H[k][2];

    float Sf[3][3];
#pragma unroll
    for (int k = 0; k < 3; k++)
#pragma unroll
        for (int l = 0; l < 3; l++)
            Sf[k][l] = H[k][0] * PHt[0][l] + H[k][1] * PHt[1][l] +
                       H[k][2] * PHt[2][l] + Rs[k * 3 + l];

    // symmetric float inverse via diagonal equilibration:
    // M = D S D with D = diag(1/sqrt(Sii)) has unit diagonal, cond ~ O(1)
    float s00 = Sf[0][0];
    float s11 = Sf[1][1];
    float s22 = Sf[2][2];
    float s01 = 0.5f * (Sf[0][1] + Sf[1][0]);
    float s02 = 0.5f * (Sf[0][2] + Sf[2][0]);
    float s12 = 0.5f * (Sf[1][2] + Sf[2][1]);
    float q0 = rsqrtf(s00), q1 = rsqrtf(s11), q2 = rsqrtf(s22);
    float m01 = s01 * q0 * q1;
    float m02 = s02 * q0 * q2;
    float m12 = s12 * q1 * q2;

    float c00 = 1.0f - m12 * m12;
    float c01 = m02 * m12 - m01;
    float c02 = m01 * m12 - m02;
    float detM = c00 + m01 * c01 + m02 * c02;
    float idetM = 1.0f / detM;
    float j00 = c00 * idetM;
    float j01 = c01 * idetM;
    float j02 = c02 * idetM;
    float j11 = (1.0f - m02 * m02) * idetM;
    float j12 = (m01 * m02 - m12) * idetM;
    float j22 = (1.0f - m01 * m01) * idetM;

    // Sinv = D * Minv * D
    float i00 = j00 * q0 * q0;
    float i01 = j01 * q0 * q1;
    float i02 = j02 * q0 * q2;
    float i11 = j11 * q1 * q1;
    float i12 = j12 * q1 * q2;
    float i22 = j22 * q2 * q2;
    // logdet(S) = log(detM * s00 * s11 * s22)
    float logdet = logf(detM * s00 * s11 * s22);

    float K[6][3];
#pragma unroll
    for (int i = 0; i < 6; i++) {
        K[i][0] = PHt[i][0] * i00 + PHt[i][1] * i01 + PHt[i][2] * i02;
        K[i][1] = PHt[i][0] * i01 + PHt[i][1] * i11 + PHt[i][2] * i12;
        K[i][2] = PHt[i][0] * i02 + PHt[i][1] * i12 + PHt[i][2] * i22;
    }

    float KH[6][3];
#pragma unroll
    for (int i = 0; i < 6; i++)
#pragma unroll
        for (int j = 0; j < 3; j++)
            KH[i][j] = K[i][0] * H[0][j] + K[i][1] * H[1][j] + K[i][2] * H[2][j];

    float* pc = reinterpret_cast<float*>(g_postcov4);
#pragma unroll
    for (int i = 0; i < 6; i++)
#pragma unroll
        for (int j = 0; j < 6; j++) {
            float v = Ps[i * 6 + j] -
                      (KH[i][0] * Ps[0 * 6 + j] + KH[i][1] * Ps[1 * 6 + j] +
                       KH[i][2] * Ps[2 * 6 + j]);
            pc[n * 36 + i * 6 + j] = v;
        }

    g_ybar[n * 3 + 0] = yb0;
    g_ybar[n * 3 + 1] = yb1;
    g_ybar[n * 3 + 2] = yb2;
#pragma unroll
    for (int i = 0; i < 6; i++) {
        g_K[n * 18 + i * 3 + 0] = K[i][0];
        g_K[n * 18 + i * 3 + 1] = K[i][1];
        g_K[n * 18 + i * 3 + 2] = K[i][2];
    }
    g_Sinv[n * 6 + 0] = i00; g_Sinv[n * 6 + 1] = i01; g_Sinv[n * 6 + 2] = i02;
    g_Sinv[n * 6 + 3] = i11; g_Sinv[n * 6 + 4] = i12; g_Sinv[n * 6 + 5] = i22;
    g_c0[n] = logf(PD_C) + logf(wts[n]) - 0.5f * (logdet + 3.0f * LOG2PI);
}

// ---------------- kernel 3: per (m,n) update; m split across blockIdx.y ---
#define MSPLIT 8
#define MCHUNK (NMEAS / MSPLIT)    // 8
__global__ void k_update(const float* __restrict__ means,
                         const float* __restrict__ meas,
                         const int* __restrict__ mask,
                         float* __restrict__ out) {
    __shared__ float zm[MCHUNK * 3];
    __shared__ int mk[MCHUNK];
    int tid = threadIdx.x;
    int m0 = blockIdx.y * MCHUNK;
    if (tid < MCHUNK * 3) zm[tid] = meas[m0 * 3 + tid];
    if (tid < MCHUNK)     mk[tid] = mask[m0 + tid];
    __syncthreads();

    int n = blockIdx.x * blockDim.x + tid;
    if (n >= NCOMP) return;

    float mu[6];
#pragma unroll
    for (int i = 0; i < 6; i++) mu[i] = means[n * 6 + i];
    float yb0 = g_ybar[n * 3 + 0];
    float yb1 = g_ybar[n * 3 + 1];
    float yb2 = g_ybar[n * 3 + 2];
    float K[18];
#pragma unroll
    for (int i = 0; i < 18; i++) K[i] = g_K[n * 18 + i];
    float s00 = g_Sinv[n * 6 + 0], s01 = g_Sinv[n * 6 + 1],
          s02 = g_Sinv[n * 6 + 2], s11 = g_Sinv[n * 6 + 3],
          s12 = g_Sinv[n * 6 + 4], s22 = g_Sinv[n * 6 + 5];
    float c0 = g_c0[n];

#pragma unroll
    for (int mm = 0; mm < MCHUNK; mm++) {
        int m = m0 + mm;
        float r0 = yb0 - zm[mm * 3 + 0];
        float r1 = yb1 - zm[mm * 3 + 1];
        float r2 = yb2 - zm[mm * 3 + 2];
        float maha = s00 * r0 * r0 + s11 * r1 * r1 + s22 * r2 * r2 +
                     2.0f * (s01 * r0 * r1 + s02 * r0 * r2 + s12 * r1 * r2);
        g_terms[m * NCOMP + n] = c0 - 0.5f * maha;

        bool on = (mk[mm] != 0);
        float p0 = 0.f, p1 = 0.f, p2 = 0.f, p3 = 0.f, p4 = 0.f, p5 = 0.f;
        if (on) {
            p0 = mu[0] - (K[0]  * r0 + K[1]  * r1 + K[2]  * r2);
            p1 = mu[1] - (K[3]  * r0 + K[4]  * r1 + K[5]  * r2);
            p2 = mu[2] - (K[6]  * r0 + K[7]  * r1 + K[8]  * r2);
            p3 = mu[3] - (K[9]  * r0 + K[10] * r1 + K[11] * r2);
            p4 = mu[4] - (K[12] * r0 + K[13] * r1 + K[14] * r2);
            p5 = mu[5] - (K[15] * r0 + K[16] * r1 + K[17] * r2);
        }
        float2* dst = reinterpret_cast<float2*>(out + ENS_OFF +
                                                (size_t)(m * NCOMP + n) * 6);
        __stcs(&dst[0], make_float2(p0, p1));
        __stcs(&dst[1], make_float2(p2, p3));
        __stcs(&dst[2], make_float2(p4, p5));
    }
}

// ---------------- kernel 4: fused logsumexp + weights ----------------
__global__ void k_lse_weights(const int* __restrict__ mask,
                              float* __restrict__ out) {
    int m = blockIdx.x;
    int tid = threadIdx.x;
    int lane = tid & 31, warp = tid >> 5;
    __shared__ float sh[32];
    __shared__ float s_logden;

    const float* terms = g_terms + m * NCOMP;

    float mx = -3.4e38f;
    for (int n = tid; n < NCOMP; n += 1024)
        mx = fmaxf(mx, terms[n]);
#pragma unroll
    for (int off = 16; off > 0; off >>= 1)
        mx = fmaxf(mx, __shfl_down_sync(0xffffffffu, mx, off));
    if (lane == 0) sh[warp] = mx;
    __syncthreads();
    if (warp == 0) {
        float v = sh[lane];
#pragma unroll
        for (int off = 16; off > 0; off >>= 1)
            v = fmaxf(v, __shfl_down_sync(0xffffffffu, v, off));
        if (lane == 0) sh[0] = v;
    }
    __syncthreads();
    float bm = sh[0];
    __syncthreads();

    float sum = 0.0f;
    for (int n = tid; n < NCOMP; n += 1024)
        sum += expf(terms[n] - bm);
#pragma unroll
    for (int off = 16; off > 0; off >>= 1)
        sum += __shfl_down_sync(0xffffffffu, sum, off);
    if (lane == 0) sh[warp] = sum;
    __syncthreads();
    if (warp == 0) {
        float v = sh[lane];
#pragma unroll
        for (int off = 16; off > 0; off >>= 1)
            v += __shfl_down_sync(0xffffffffu, v, off);
        if (lane == 0) {
            float lse = bm + logf(v);
            float a = logf(CLUTTER_C);
            float hi = fmaxf(a, lse), lo = fminf(a, lse);
            s_logden = hi + log1pf(expf(lo - hi));
        }
    }
    __syncthreads();

    float ld = s_logden;
    bool on = (mask[m] != 0);
    float* wout = out + W_OFF + m * NCOMP;
    for (int n = tid; n < NCOMP; n += 1024) {
        float w = on ? expf(terms[n] - ld) : 0.0f;
        __stcs(wout + n, w);
    }
}

// ---------------- kernel 5: covariance broadcast ----------------
#define MGRP 8
#define MGROUPS (NMEAS / MGRP)   // 8
__global__ void k_covbcast(const int* __restrict__ mask,
                           float* __restrict__ out) {
    __shared__ int mk[MGRP];
    int m0 = blockIdx.y * MGRP;
    if (threadIdx.x < MGRP) mk[threadIdx.x] = mask[m0 + threadIdx.x];
    __syncthreads();

    int idx = blockIdx.x * blockDim.x + threadIdx.x;
    if (idx >= NCOMP * 9) return;

    float4 v = __ldg(&g_postcov4[idx]);
    const float4 z = make_float4(0.f, 0.f, 0.f, 0.f);
    float4* dst = reinterpret_cast<float4*>(out + COV_OFF);
#pragma unroll
    for (int k = 0; k < MGRP; k++) {
        int m = m0 + k;
        float4 w = (mk[k] != 0) ? v : z;
        __stcs(&dst[(size_t)m * (NCOMP * 9) + idx], w);
    }
}

// ---------------- launch: fork covbcast onto a side stream ----------------
static cudaStream_t g_s2 = nullptr;
static cudaEvent_t  g_evFork = nullptr, g_evJoin = nullptr;

extern "C" void kernel_launch(void* const* d_in, const int* in_sizes, int n_in,
                              void* d_out, int out_size) {
    const float* means = (const float*)d_in[0];
    const float* wts   = (const float*)d_in[1];
    const float* meas  = (const float*)d_in[2];
    const float* Rm    = (const float*)d_in[3];
    const int*   mask  = (const int*)d_in[4];
    float* out = (float*)d_out;

    if (g_s2 == nullptr) {
        cudaStreamCreateWithFlags(&g_s2, cudaStreamNonBlocking);
        cudaEventCreateWithFlags(&g_evFork, cudaEventDisableTiming);
        cudaEventCreateWithFlags(&g_evJoin, cudaEventDisableTiming);
    }

    // main (capture) stream: reductions + linearization
    k_cov_partial<<<NPART, 256>>>(means);
    k_cov_final<<<1, 64>>>();
    k_pern<<<(NCOMP + 127) / 128, 128>>>(means, wts, Rm);

    // fork: covbcast depends only on k_pern's post_cov table + mask
    cudaEventRecord(g_evFork, 0);
    cudaStreamWaitEvent(g_s2, g_evFork, 0);
    dim3 gc((NCOMP * 9 + 255) / 256, MGROUPS);
    k_covbcast<<<gc, 256, 0, g_s2>>>(mask, out);
    cudaEventRecord(g_evJoin, g_s2);

    // main stream continues with the update chain concurrently
    dim3 gu((NCOMP + 255) / 256, MSPLIT);
    k_update<<<gu, 256>>>(means, meas, mask, out);
    k_lse_weights<<<NMEAS, 1024>>>(mask, out);

    // join side branch back into the capture stream
    cudaStreamWaitEvent(0, g_evJoin, 0);
}

// round 11
// speedup vs baseline: 2.2345x; 1.0493x over previous
#include <cuda_runtime.h>
#include <math.h>

#define NCOMP 20000
#define NMEAS 64
#define SDIM 6
#define MDIM 3
#define NPART 128
#define LOG2PI 1.8378770664093453f
#define PD_C 0.98f
#define CLUTTER_C 1e-4f

#define ENS_OFF 0
#define W_OFF   (NMEAS * NCOMP * SDIM)
#define COV_OFF (W_OFF + NMEAS * NCOMP)

// ---------------- device scratch ----------------
__device__ float  g_part[NPART * 27];
__device__ int    g_ctr = 0;            // last-block counter (reset after use)
__device__ float  g_P[36];
__device__ float4 g_postcov4[NCOMP * 9];
__device__ float  g_terms[NMEAS * NCOMP];

// ---------------- kernel 1: fused anchored covariance + finalize ----------
__global__ void k_cov(const float* __restrict__ means) {
    float a[6];
#pragma unroll
    for (int i = 0; i < 6; i++) a[i] = __ldg(&means[i]);

    float v[27];
#pragma unroll
    for (int k = 0; k < 27; k++) v[k] = 0.0f;

    for (int r = blockIdx.x * blockDim.x + threadIdx.x; r < NCOMP;
         r += gridDim.x * blockDim.x) {
        float d[6];
#pragma unroll
        for (int i = 0; i < 6; i++) d[i] = means[r * 6 + i] - a[i];
#pragma unroll
        for (int i = 0; i < 6; i++) v[i] += d[i];
        int idx = 6;
#pragma unroll
        for (int i = 0; i < 6; i++)
#pragma unroll
            for (int j = i; j < 6; j++)
                v[idx++] = fmaf(d[i], d[j], v[idx]);
    }

    int lane = threadIdx.x & 31;
    int warp = threadIdx.x >> 5;
    __shared__ float sh[8][27];
#pragma unroll
    for (int k = 0; k < 27; k++) {
        float s = v[k];
#pragma unroll
        for (int off = 16; off > 0; off >>= 1)
            s += __shfl_down_sync(0xffffffffu, s, off);
        if (lane == 0) sh[warp][k] = s;
    }
    __syncthreads();
    if (threadIdx.x < 27) {
        float s = 0.0f;
#pragma unroll
        for (int w = 0; w < 8; w++) s += sh[w][threadIdx.x];
        g_part[blockIdx.x * 27 + threadIdx.x] = s;
    }
    __syncthreads();          // ALL partial writes of this block complete
    __threadfence();          // ... and visible device-wide before ticket

    // last-block finalize
    __shared__ int s_last;
    if (threadIdx.x == 0) {
        int c = atomicAdd(&g_ctr, 1);
        s_last = (c == NPART - 1);
    }
    __syncthreads();
    if (!s_last) return;
    __threadfence();   // acquire: all other blocks' partials visible

    __shared__ double acc[27];
    int t = threadIdx.x;
    if (t < 27) {
        double s = 0.0;
        for (int b = 0; b < NPART; b++) s += (double)g_part[b * 27 + t];
        acc[t] = s;
    }
    __syncthreads();
    if (t < 36) {
        int i = t / 6, j = t % 6;
        double mdi = acc[i] / (double)NCOMP;
        double mdj = acc[j] / (double)NCOMP;
        int ii = (i < j) ? i : j;
        int jj = (i < j) ? j : i;
        int tri = 6 + (ii * (13 - ii)) / 2 + (jj - ii);
        double c = (acc[tri] - (double)NCOMP * mdi * mdj) / (double)(NCOMP - 1);
        double bw = pow(4.0 / ((double)NCOMP * (SDIM + 2)), 2.0 / (SDIM + 4));
        double d = (double)(i - j);
        double loc = exp(-(d * d) / (2.0 * 3.0 * 3.0));
        g_P[i * 6 + j] = (float)(bw * c * loc);
    }
    if (t == 0) g_ctr = 0;   // restore invariant for graph replay
}

// ---------------- kernel 2: fused linearization + per-measurement update --
__global__ void __launch_bounds__(128)
k_pern_update(const float* __restrict__ means,
              const float* __restrict__ wts,
              const float* __restrict__ Rm,
              const float* __restrict__ meas,
              const int* __restrict__ mask,
              float* __restrict__ out) {
    __shared__ float Ps[36];
    __shared__ float Rs[9];
    __shared__ float zm[NMEAS * 3];
    __shared__ int mk[NMEAS];
    int tid = threadIdx.x;
    if (tid < 36) Ps[tid] = g_P[tid];
    if (tid < 9)  Rs[tid] = Rm[tid];
    for (int i = tid; i < NMEAS * 3; i += 128) zm[i] = meas[i];  // 192 > 128!
    if (tid < NMEAS) mk[tid] = mask[tid];
    __syncthreads();

    int n = blockIdx.x * blockDim.x + tid;
    if (n >= NCOMP) return;

    float mu[6];
#pragma unroll
    for (int i = 0; i < 6; i++) mu[i] = means[n * 6 + i];
    float x = mu[0], y = mu[1], z = mu[2];

    float rxy2 = x * x + y * y;
    float rho2 = rxy2 + z * z;
    float rho  = sqrtf(rho2);
    float rxy  = sqrtf(rxy2);

    float yb0 = rho;
    float yb1 = atan2f(y, x);
    float yb2 = asinf(z / rho);

    float H[3][3];
    float irho = 1.0f / rho;
    H[0][0] = x * irho; H[0][1] = y * irho; H[0][2] = z * irho;
    float irxy2 = 1.0f / rxy2;
    H[1][0] = -y * irxy2; H[1][1] = x * irxy2; H[1][2] = 0.0f;
    float den = 1.0f / (rho2 * rxy);
    H[2][0] = -x * z * den; H[2][1] = -y * z * den; H[2][2] = rxy / rho2;

    float PHt[6][3];
#pragma unroll
    for (int i = 0; i < 6; i++)
#pragma unroll
        for (int k = 0; k < 3; k++)
            PHt[i][k] = Ps[i * 6 + 0] * H[k][0] + Ps[i * 6 + 1] * H[k][1] +
                        Ps[i * 6 + 2] * H[k][2];

    float Sf[3][3];
#pragma unroll
    for (int k = 0; k < 3; k++)
#pragma unroll
        for (int l = 0; l < 3; l++)
            Sf[k][l] = H[k][0] * PHt[0][l] + H[k][1] * PHt[1][l] +
                       H[k][2] * PHt[2][l] + Rs[k * 3 + l];

    // equilibrated symmetric 3x3 inverse (float)
    float s00 = Sf[0][0], s11 = Sf[1][1], s22 = Sf[2][2];
    float s01 = 0.5f * (Sf[0][1] + Sf[1][0]);
    float s02 = 0.5f * (Sf[0][2] + Sf[2][0]);
    float s12 = 0.5f * (Sf[1][2] + Sf[2][1]);
    float q0 = rsqrtf(s00), q1 = rsqrtf(s11), q2 = rsqrtf(s22);
    float m01 = s01 * q0 * q1;
    float m02 = s02 * q0 * q2;
    float m12 = s12 * q1 * q2;

    float c00 = 1.0f - m12 * m12;
    float c01 = m02 * m12 - m01;
    float c02 = m01 * m12 - m02;
    float detM = c00 + m01 * c01 + m02 * c02;
    float idetM = 1.0f / detM;
    float i00 = c00 * idetM * q0 * q0;
    float i01 = c01 * idetM * q0 * q1;
    float i02 = c02 * idetM * q0 * q2;
    float i11 = (1.0f - m02 * m02) * idetM * q1 * q1;
    float i12 = (m01 * m02 - m12) * idetM * q1 * q2;
    float i22 = (1.0f - m01 * m01) * idetM * q2 * q2;
    float logdet = logf(detM * s00 * s11 * s22);

    float K[6][3];
#pragma unroll
    for (int i = 0; i < 6; i++) {
        K[i][0] = PHt[i][0] * i00 + PHt[i][1] * i01 + PHt[i][2] * i02;
        K[i][1] = PHt[i][0] * i01 + PHt[i][1] * i11 + PHt[i][2] * i12;
        K[i][2] = PHt[i][0] * i02 + PHt[i][1] * i12 + PHt[i][2] * i22;
    }

    float KH[6][3];
#pragma unroll
    for (int i = 0; i < 6; i++)
#pragma unroll
        for (int j = 0; j < 3; j++)
            KH[i][j] = K[i][0] * H[0][j] + K[i][1] * H[1][j] + K[i][2] * H[2][j];

    float* pc = reinterpret_cast<float*>(g_postcov4);
#pragma unroll
    for (int i = 0; i < 6; i++)
#pragma unroll
        for (int j = 0; j < 6; j++) {
            float v = Ps[i * 6 + j] -
                      (KH[i][0] * Ps[0 * 6 + j] + KH[i][1] * Ps[1 * 6 + j] +
                       KH[i][2] * Ps[2 * 6 + j]);
            pc[n * 36 + i * 6 + j] = v;
        }

    float c0 = logf(PD_C) + logf(wts[n]) - 0.5f * (logdet + 3.0f * LOG2PI);

    // ---- fused per-measurement update: ensemble points + log terms ----
#pragma unroll 4
    for (int m = 0; m < NMEAS; m++) {
        float r0 = yb0 - zm[m * 3 + 0];
        float r1 = yb1 - zm[m * 3 + 1];
        float r2 = yb2 - zm[m * 3 + 2];
        float maha = i00 * r0 * r0 + i11 * r1 * r1 + i22 * r2 * r2 +
                     2.0f * (i01 * r0 * r1 + i02 * r0 * r2 + i12 * r1 * r2);
        g_terms[m * NCOMP + n] = c0 - 0.5f * maha;

        bool on = (mk[m] != 0);
        float p0 = 0.f, p1 = 0.f, p2 = 0.f, p3 = 0.f, p4 = 0.f, p5 = 0.f;
        if (on) {
            p0 = mu[0] - (K[0][0] * r0 + K[0][1] * r1 + K[0][2] * r2);
            p1 = mu[1] - (K[1][0] * r0 + K[1][1] * r1 + K[1][2] * r2);
            p2 = mu[2] - (K[2][0] * r0 + K[2][1] * r1 + K[2][2] * r2);
            p3 = mu[3] - (K[3][0] * r0 + K[3][1] * r1 + K[3][2] * r2);
            p4 = mu[4] - (K[4][0] * r0 + K[4][1] * r1 + K[4][2] * r2);
            p5 = mu[5] - (K[5][0] * r0 + K[5][1] * r1 + K[5][2] * r2);
        }
        float2* dst = reinterpret_cast<float2*>(out + ENS_OFF +
                                                (size_t)(m * NCOMP + n) * 6);
        __stcs(&dst[0], make_float2(p0, p1));
        __stcs(&dst[1], make_float2(p2, p3));
        __stcs(&dst[2], make_float2(p4, p5));
    }
}

// ---------------- kernel 3: fused logsumexp + weights ----------------
__global__ void k_lse_weights(const int* __restrict__ mask,
                              float* __restrict__ out) {
    int m = blockIdx.x;
    int tid = threadIdx.x;
    int lane = tid & 31, warp = tid >> 5;
    __shared__ float sh[32];
    __shared__ float s_logden;

    const float* terms = g_terms + m * NCOMP;

    float mx = -3.4e38f;
    for (int n = tid; n < NCOMP; n += 1024)
        mx = fmaxf(mx, terms[n]);
#pragma unroll
    for (int off = 16; off > 0; off >>= 1)
        mx = fmaxf(mx, __shfl_down_sync(0xffffffffu, mx, off));
    if (lane == 0) sh[warp] = mx;
    __syncthreads();
    if (warp == 0) {
        float v = sh[lane];
#pragma unroll
        for (int off = 16; off > 0; off >>= 1)
            v = fmaxf(v, __shfl_down_sync(0xffffffffu, v, off));
        if (lane == 0) sh[0] = v;
    }
    __syncthreads();
    float bm = sh[0];
    __syncthreads();

    float sum = 0.0f;
    for (int n = tid; n < NCOMP; n += 1024)
        sum += expf(terms[n] - bm);
#pragma unroll
    for (int off = 16; off > 0; off >>= 1)
        sum += __shfl_down_sync(0xffffffffu, sum, off);
    if (lane == 0) sh[warp] = sum;
    __syncthreads();
    if (warp == 0) {
        float v = sh[lane];
#pragma unroll
        for (int off = 16; off > 0; off >>= 1)
            v += __shfl_down_sync(0xffffffffu, v, off);
        if (lane == 0) {
            float lse = bm + logf(v);
            float a = logf(CLUTTER_C);
            float hi = fmaxf(a, lse), lo = fminf(a, lse);
            s_logden = hi + log1pf(expf(lo - hi));
        }
    }
    __syncthreads();

    float ld = s_logden;
    bool on = (mask[m] != 0);
    float* wout = out + W_OFF + m * NCOMP;
    for (int n = tid; n < NCOMP; n += 1024) {
        float w = on ? expf(terms[n] - ld) : 0.0f;
        __stcs(wout + n, w);
    }
}

// ---------------- kernel 4: covariance broadcast ----------------
#define MGRP 8
#define MGROUPS (NMEAS / MGRP)   // 8
__global__ void k_covbcast(const int* __restrict__ mask,
                           float* __restrict__ out) {
    __shared__ int mk[MGRP];
    int m0 = blockIdx.y * MGRP;
    if (threadIdx.x < MGRP) mk[threadIdx.x] = mask[m0 + threadIdx.x];
    __syncthreads();

    int idx = blockIdx.x * blockDim.x + threadIdx.x;
    if (idx >= NCOMP * 9) return;

    float4 v = __ldg(&g_postcov4[idx]);
    const float4 z = make_float4(0.f, 0.f, 0.f, 0.f);
    float4* dst = reinterpret_cast<float4*>(out + COV_OFF);
#pragma unroll
    for (int k = 0; k < MGRP; k++) {
        int m = m0 + k;
        float4 w = (mk[k] != 0) ? v : z;
        __stcs(&dst[(size_t)m * (NCOMP * 9) + idx], w);
    }
}

// ---------------- launch: fork covbcast onto a side stream ----------------
static cudaStream_t g_s2 = nullptr;
static cudaEvent_t  g_evFork = nullptr, g_evJoin = nullptr;

extern "C" void kernel_launch(void* const* d_in, const int* in_sizes, int n_in,
                              void* d_out, int out_size) {
    const float* means = (const float*)d_in[0];
    const float* wts   = (const float*)d_in[1];
    const float* meas  = (const float*)d_in[2];
    const float* Rm    = (const float*)d_in[3];
    const int*   mask  = (const int*)d_in[4];
    float* out = (float*)d_out;

    if (g_s2 == nullptr) {
        cudaStreamCreateWithFlags(&g_s2, cudaStreamNonBlocking);
        cudaEventCreateWithFlags(&g_evFork, cudaEventDisableTiming);
        cudaEventCreateWithFlags(&g_evJoin, cudaEventDisableTiming);
    }

    // main stream: fused covariance, then fused linearization+update
    k_cov<<<NPART, 256>>>(means);
    k_pern_update<<<(NCOMP + 127) / 128, 128>>>(means, wts, Rm, meas, mask, out);

    // fork: covbcast depends only on post_cov table + mask
    cudaEventRecord(g_evFork, 0);
    cudaStreamWaitEvent(g_s2, g_evFork, 0);
    dim3 gc((NCOMP * 9 + 255) / 256, MGROUPS);
    k_covbcast<<<gc, 256, 0, g_s2>>>(mask, out);
    cudaEventRecord(g_evJoin, g_s2);

    // main stream: logsumexp + weights overlaps the broadcast
    k_lse_weights<<<NMEAS, 1024>>>(mask, out);

    cudaStreamWaitEvent(0, g_evJoin, 0);
}